// round 10
// baseline (speedup 1.0000x reference)
#include <cstdint>
#include <cuda_runtime.h>
#include <cuda_bf16.h>
#include <mma.h>

using namespace nvcuda;

// Problem constants
#define BB      256
#define TENC    25
#define XDIM_   512
#define SDIM_   512
#define ADIM_   512
#define YDIM_   6625
#define TDEC    25
#define EMBIN   300

// ---------------------------------------------------------------------------
// Static device scratch
// ---------------------------------------------------------------------------
__device__ __align__(256) float g_Wcat[2048 * 512];      // [sEmbed_w ; gru_w_hh]
__device__ __align__(256) float g_bcat[2048];
__device__ __align__(256) float g_EbufPart[16 * 256 * 300];
__device__ __align__(256) float g_emb[256 * 300];
__device__ __align__(256) float g_XP[6400 * 512];        // xProj, row = b*25+t
__device__ __align__(256) float g_Yp[6400 * 512];        // yProj, row = t*256+b
__device__ __align__(256) float g_GIY[6400 * 1536];      // precomputed gi (yProj part + b_ih)
__device__ __align__(256) float g_states[26 * 256 * 512];// state0 .. state25
__device__ __align__(256) float g_C1[256 * 2048];        // [sProj | gh] per step
__device__ __align__(256) float g_ctx[256 * 512];        // attention context

// ---------------------------------------------------------------------------
// cp.async helpers
// ---------------------------------------------------------------------------
__device__ __forceinline__ void cp_async16(void* smem_dst, const void* gptr, bool pred)
{
    unsigned int sa = (unsigned int)__cvta_generic_to_shared(smem_dst);
    int bytes = pred ? 16 : 0;
    asm volatile("cp.async.ca.shared.global [%0], [%1], 16, %2;\n"
                 :: "r"(sa), "l"(gptr), "r"(bytes));
}

// ---------------------------------------------------------------------------
// Pipelined TF32 wmma GEMM (NT): C = A @ W^T + bias. Block 128x128, BK=16,
// 2-stage cp.async double buffering, 8 warps (2x4), warp tile 64x32.
// Bias folded into accumulator init. Direct fragment stores only for the
// non-permuted interior path (even ldc => 8B-aligned v2 stores). The permuted
// fc output has odd row stride (25*6625) so it always uses the staged
// scalar-store path (alignment-safe).
// Requires M % 128 == 0, K % 16 == 0.
// ---------------------------------------------------------------------------
__global__ __launch_bounds__(256)
void wgemm(const float* __restrict__ A, int lda,
           const float* __restrict__ W, int ldw,
           const float* __restrict__ bias,
           float* __restrict__ C, int ldc,
           int M, int N, int K, int permuted)
{
    __shared__ float sm[10240];     // 40 KB
    const int LDS = 20;
    // stage s: A at s*5120, W at s*5120 + 2560  ([128][20] each)

    int tid  = threadIdx.x;
    int warp = tid >> 5;
    int wr   = warp >> 2;           // 0..1
    int wc   = warp & 3;            // 0..3
    int m0 = blockIdx.y * 128;
    int n0 = blockIdx.x * 128;

    // ---- bias -> accumulator init (broadcast tile in smem) ----
    {
        float* Bs = sm;             // [16][136]
        const int LDB = 136;
        for (int i = tid; i < 16 * 128; i += 256) {
            int r = i >> 7, c = i & 127;
            int n = n0 + c;
            Bs[r * LDB + c] = (bias && n < N) ? bias[n] : 0.f;
        }
        __syncthreads();
    }
    wmma::fragment<wmma::accumulator, 16, 16, 8, float> c_frag[4][2];
    {
        float* Bs = sm;
        const int LDB = 136;
#pragma unroll
        for (int j = 0; j < 2; j++) {
            wmma::load_matrix_sync(c_frag[0][j], &Bs[wc * 32 + j * 16], LDB, wmma::mem_row_major);
#pragma unroll
            for (int i = 1; i < 4; i++)
#pragma unroll
                for (int t = 0; t < c_frag[0][j].num_elements; t++)
                    c_frag[i][j].x[t] = c_frag[0][j].x[t];
        }
        __syncthreads();
    }

    int nIter = K >> 4;

    auto load_stage = [&](int k0, int s) {
        float* As = sm + s * 5120;
        float* Ws = sm + s * 5120 + 2560;
#pragma unroll
        for (int i = 0; i < 2; i++) {
            int idx = tid + i * 256;
            int r  = idx >> 2;
            int c4 = (idx & 3) * 4;
            cp_async16(&As[r * LDS + c4], &A[(size_t)(m0 + r) * lda + k0 + c4], true);
            int gn = n0 + r;
            cp_async16(&Ws[r * LDS + c4], &W[(size_t)gn * ldw + k0 + c4], gn < N);
        }
        asm volatile("cp.async.commit_group;\n");
    };

    load_stage(0, 0);

    for (int it = 0; it < nIter; it++) {
        if (it + 1 < nIter) {
            load_stage((it + 1) << 4, (it + 1) & 1);
            asm volatile("cp.async.wait_group 1;\n");
        } else {
            asm volatile("cp.async.wait_group 0;\n");
        }
        __syncthreads();

        float* As = sm + (it & 1) * 5120;
        float* Ws = sm + (it & 1) * 5120 + 2560;
#pragma unroll
        for (int ks = 0; ks < 16; ks += 8) {
            wmma::fragment<wmma::matrix_a, 16, 16, 8, wmma::precision::tf32, wmma::row_major> a_frag[4];
            wmma::fragment<wmma::matrix_b, 16, 16, 8, wmma::precision::tf32, wmma::col_major> b_frag[2];
#pragma unroll
            for (int i = 0; i < 4; i++) {
                wmma::load_matrix_sync(a_frag[i], &As[(wr * 64 + i * 16) * LDS + ks], LDS);
#pragma unroll
                for (int t = 0; t < a_frag[i].num_elements; t++)
                    a_frag[i].x[t] = wmma::__float_to_tf32(a_frag[i].x[t]);
            }
#pragma unroll
            for (int j = 0; j < 2; j++) {
                wmma::load_matrix_sync(b_frag[j], &Ws[(wc * 32 + j * 16) * LDS + ks], LDS);
#pragma unroll
                for (int t = 0; t < b_frag[j].num_elements; t++)
                    b_frag[j].x[t] = wmma::__float_to_tf32(b_frag[j].x[t]);
            }
#pragma unroll
            for (int i = 0; i < 4; i++)
#pragma unroll
                for (int j = 0; j < 2; j++)
                    wmma::mma_sync(c_frag[i][j], a_frag[i], b_frag[j], c_frag[i][j]);
        }
        __syncthreads();
    }

    if (!permuted && n0 + 128 <= N) {
        // Fast path: direct fragment stores to global (even ldc, 8B-aligned).
#pragma unroll
        for (int i = 0; i < 4; i++) {
            int m = m0 + wr * 64 + i * 16;
#pragma unroll
            for (int j = 0; j < 2; j++) {
                int n = n0 + wc * 32 + j * 16;
                wmma::store_matrix_sync(&C[(size_t)m * ldc + n],
                                        c_frag[i][j], ldc, wmma::mem_row_major);
            }
        }
    } else {
        // Staged path: shared staging + guarded scalar writes (alignment-safe).
        float* Cs = sm;             // [64][132]
        const int LDCS = 132;
#pragma unroll
        for (int p = 0; p < 2; p++) {
            if (wr == p) {
#pragma unroll
                for (int i = 0; i < 4; i++)
#pragma unroll
                    for (int j = 0; j < 2; j++)
                        wmma::store_matrix_sync(&Cs[(i * 16) * LDCS + wc * 32 + j * 16],
                                                c_frag[i][j], LDCS, wmma::mem_row_major);
            }
            __syncthreads();
#pragma unroll
            for (int i = 0; i < 32; i++) {
                int idx = tid + i * 256;
                int r = idx >> 7;
                int c = idx & 127;
                int m = m0 + p * 64 + r;
                int n = n0 + c;
                if (n < N) {
                    float v = Cs[r * LDCS + c];
                    if (permuted) {
                        int b = m & 255;
                        int t = m >> 8;
                        C[(size_t)b * (TDEC * YDIM_) + (size_t)t * YDIM_ + n] = v;
                    } else {
                        C[(size_t)m * ldc + n] = v;
                    }
                }
            }
            __syncthreads();
        }
    }
}

// ---------------------------------------------------------------------------
// Small TF32 wmma GEMM (NT) for the decode loop: block 64x64, 4 warps (2x2),
// warp tile 32x32, BK=32. C = A @ W^T (+bias[n]).
// ---------------------------------------------------------------------------
__global__ __launch_bounds__(128)
void wgemm_small(const float* __restrict__ A, int lda,
                 const float* __restrict__ W, int ldw,
                 const float* __restrict__ bias,
                 float* __restrict__ C, int ldc, int K)
{
    __shared__ float sm[4608];
    const int LDS = 36;
    float* As = sm;                 // [64][36]
    float* Ws = sm + 2304;

    int tid  = threadIdx.x;
    int warp = tid >> 5;
    int wr   = warp >> 1;           // 0..1
    int wc   = warp & 1;            // 0..1
    int m0 = blockIdx.y * 64;
    int n0 = blockIdx.x * 64;

    wmma::fragment<wmma::accumulator, 16, 16, 8, float> c_frag[2][2];
#pragma unroll
    for (int i = 0; i < 2; i++)
#pragma unroll
        for (int j = 0; j < 2; j++)
            wmma::fill_fragment(c_frag[i][j], 0.0f);

    for (int k0 = 0; k0 < K; k0 += 32) {
#pragma unroll
        for (int i = 0; i < 4; i++) {
            int idx = tid + i * 128;        // 0..511
            int r  = idx >> 3;              // 0..63
            int c4 = (idx & 7) * 4;         // 0..28
            *(float4*)&As[r * LDS + c4] = *(const float4*)&A[(size_t)(m0 + r) * lda + k0 + c4];
            *(float4*)&Ws[r * LDS + c4] = *(const float4*)&W[(size_t)(n0 + r) * ldw + k0 + c4];
        }
        __syncthreads();
#pragma unroll
        for (int ks = 0; ks < 32; ks += 8) {
            wmma::fragment<wmma::matrix_a, 16, 16, 8, wmma::precision::tf32, wmma::row_major> a_frag[2];
            wmma::fragment<wmma::matrix_b, 16, 16, 8, wmma::precision::tf32, wmma::col_major> b_frag[2];
#pragma unroll
            for (int i = 0; i < 2; i++) {
                wmma::load_matrix_sync(a_frag[i], &As[(wr * 32 + i * 16) * LDS + ks], LDS);
#pragma unroll
                for (int t = 0; t < a_frag[i].num_elements; t++)
                    a_frag[i].x[t] = wmma::__float_to_tf32(a_frag[i].x[t]);
            }
#pragma unroll
            for (int j = 0; j < 2; j++) {
                wmma::load_matrix_sync(b_frag[j], &Ws[(wc * 32 + j * 16) * LDS + ks], LDS);
#pragma unroll
                for (int t = 0; t < b_frag[j].num_elements; t++)
                    b_frag[j].x[t] = wmma::__float_to_tf32(b_frag[j].x[t]);
            }
#pragma unroll
            for (int i = 0; i < 2; i++)
#pragma unroll
                for (int j = 0; j < 2; j++)
                    wmma::mma_sync(c_frag[i][j], a_frag[i], b_frag[j], c_frag[i][j]);
        }
        __syncthreads();
    }

    // Epilogue via shared staging
    float* Cs = sm;                 // [64][68]
    const int LDCS = 68;
#pragma unroll
    for (int i = 0; i < 2; i++)
#pragma unroll
        for (int j = 0; j < 2; j++)
            wmma::store_matrix_sync(&Cs[(wr * 32 + i * 16) * LDCS + wc * 32 + j * 16],
                                    c_frag[i][j], LDCS, wmma::mem_row_major);
    __syncthreads();
#pragma unroll
    for (int i = 0; i < 32; i++) {
        int idx = tid + i * 128;            // 0..4095
        int r = idx >> 6;
        int c = idx & 63;
        int m = m0 + r, n = n0 + c;
        float v = Cs[r * LDCS + c];
        if (bias)   v += bias[n];
        C[(size_t)m * ldc + n] = v;
    }
}

// ---------------------------------------------------------------------------
// Fused GI GEMM + GRU gates. Grid (8 j-tiles, 4 m-tiles), 128 threads.
// Each block owns a 64(batch) x 64(gate-col) tile across ALL 3 gate slices:
//   slice s: gi = ctx @ Wih2[s*512+j]^T + GIY[m][s*512+j], gh from g_C1.
//   s=0 -> r, s=1 -> z, s=2 -> n, then state update written directly.
// ---------------------------------------------------------------------------
__global__ __launch_bounds__(128)
void gi3_gru(const float* __restrict__ ctx,
             const float* __restrict__ Wih2,      // gru_w_ih + 512, row stride 1024
             const float* __restrict__ GIYt,      // + t*256*1536
             const float* __restrict__ state_in,
             float* __restrict__ state_out)
{
    __shared__ float sm[4608];
    const int LDS = 36;
    float* As = sm;
    float* Ws = sm + 2304;
    __shared__ float Cs[64 * 68];
    const int LDCS = 68;

    int tid  = threadIdx.x;
    int warp = tid >> 5;
    int wr   = warp >> 1;
    int wc   = warp & 1;
    int m0 = blockIdx.y * 64;
    int j0 = blockIdx.x * 64;

    float rreg[32], zreg[32];

    for (int slice = 0; slice < 3; slice++) {
        wmma::fragment<wmma::accumulator, 16, 16, 8, float> c_frag[2][2];
#pragma unroll
        for (int i = 0; i < 2; i++)
#pragma unroll
            for (int j = 0; j < 2; j++)
                wmma::fill_fragment(c_frag[i][j], 0.0f);

        const float* Wbase = Wih2 + (size_t)(slice * 512 + j0) * 1024;

        for (int k0 = 0; k0 < 512; k0 += 32) {
#pragma unroll
            for (int i = 0; i < 4; i++) {
                int idx = tid + i * 128;
                int r  = idx >> 3;
                int c4 = (idx & 7) * 4;
                *(float4*)&As[r * LDS + c4] = *(const float4*)&ctx[(size_t)(m0 + r) * 512 + k0 + c4];
                *(float4*)&Ws[r * LDS + c4] = *(const float4*)&Wbase[(size_t)r * 1024 + k0 + c4];
            }
            __syncthreads();
#pragma unroll
            for (int ks = 0; ks < 32; ks += 8) {
                wmma::fragment<wmma::matrix_a, 16, 16, 8, wmma::precision::tf32, wmma::row_major> a_frag[2];
                wmma::fragment<wmma::matrix_b, 16, 16, 8, wmma::precision::tf32, wmma::col_major> b_frag[2];
#pragma unroll
                for (int i = 0; i < 2; i++) {
                    wmma::load_matrix_sync(a_frag[i], &As[(wr * 32 + i * 16) * LDS + ks], LDS);
#pragma unroll
                    for (int t = 0; t < a_frag[i].num_elements; t++)
                        a_frag[i].x[t] = wmma::__float_to_tf32(a_frag[i].x[t]);
                }
#pragma unroll
                for (int j = 0; j < 2; j++) {
                    wmma::load_matrix_sync(b_frag[j], &Ws[(wc * 32 + j * 16) * LDS + ks], LDS);
#pragma unroll
                    for (int t = 0; t < b_frag[j].num_elements; t++)
                        b_frag[j].x[t] = wmma::__float_to_tf32(b_frag[j].x[t]);
                }
#pragma unroll
                for (int i = 0; i < 2; i++)
#pragma unroll
                    for (int j = 0; j < 2; j++)
                        wmma::mma_sync(c_frag[i][j], a_frag[i], b_frag[j], c_frag[i][j]);
            }
            __syncthreads();
        }

        // stage this slice's tile
#pragma unroll
        for (int i = 0; i < 2; i++)
#pragma unroll
            for (int j = 0; j < 2; j++)
                wmma::store_matrix_sync(&Cs[(wr * 32 + i * 16) * LDCS + wc * 32 + j * 16],
                                        c_frag[i][j], LDCS, wmma::mem_row_major);
        __syncthreads();

        // per-thread gate math on 32 elements
#pragma unroll
        for (int i = 0; i < 32; i++) {
            int idx = tid + i * 128;
            int r = idx >> 6;
            int c = idx & 63;
            int m = m0 + r;
            int j = j0 + c;
            float gi = Cs[r * LDCS + c] + GIYt[(size_t)m * 1536 + slice * 512 + j];
            float gh = g_C1[(size_t)m * 2048 + 512 + slice * 512 + j];
            if (slice == 0) {
                rreg[i] = 1.f / (1.f + __expf(-(gi + gh)));
            } else if (slice == 1) {
                zreg[i] = 1.f / (1.f + __expf(-(gi + gh)));
            } else {
                float n = tanhf(gi + rreg[i] * gh);
                float z = zreg[i];
                float s = state_in[(size_t)m * 512 + j];
                state_out[(size_t)m * 512 + j] = (1.f - z) * n + z * s;
            }
        }
        __syncthreads();
    }
}

// ---------------------------------------------------------------------------
// fp32 SGEMM 64x64 (prologue only: embed split-K, state0)
// ---------------------------------------------------------------------------
__global__ __launch_bounds__(256)
void sgemm64(const float* __restrict__ A, int lda,
             const float* __restrict__ W, int ldw,
             const float* __restrict__ bias,
             const float* __restrict__ addend, int ldadd,
             float* __restrict__ C, int ldc,
             int M, int N, int K, int Kc)
{
    __shared__ float As[16][68];
    __shared__ float Ws[16][68];

    int tid = threadIdx.x;
    int tx = tid & 15, ty = tid >> 4;
    int m0 = blockIdx.y * 64, n0 = blockIdx.x * 64;

    int kstart = 0, kend = K;
    float* Cp = C;
    if (Kc > 0) {
        kstart = blockIdx.z * Kc;
        kend = min(K, kstart + Kc);
        Cp = C + (size_t)blockIdx.z * (size_t)M * (size_t)ldc;
    }

    float acc[4][4];
#pragma unroll
    for (int i = 0; i < 4; i++)
#pragma unroll
        for (int j = 0; j < 4; j++) acc[i][j] = 0.f;

    for (int k0 = kstart; k0 < kend; k0 += 16) {
#pragma unroll
        for (int i = 0; i < 4; i++) {
            int idx = tid + i * 256;
            int r = idx >> 4, kk = idx & 15;
            int gk = k0 + kk;
            int gm = m0 + r;
            As[kk][r] = (gm < M && gk < kend) ? A[(size_t)gm * lda + gk] : 0.f;
            int gn = n0 + r;
            Ws[kk][r] = (gn < N && gk < kend) ? W[(size_t)gn * ldw + gk] : 0.f;
        }
        __syncthreads();
#pragma unroll
        for (int kk = 0; kk < 16; kk++) {
            float4 a = *(const float4*)&As[kk][ty * 4];
            float4 b = *(const float4*)&Ws[kk][tx * 4];
            float av[4] = {a.x, a.y, a.z, a.w};
            float bv[4] = {b.x, b.y, b.z, b.w};
#pragma unroll
            for (int i = 0; i < 4; i++)
#pragma unroll
                for (int j = 0; j < 4; j++)
                    acc[i][j] = fmaf(av[i], bv[j], acc[i][j]);
        }
        __syncthreads();
    }

#pragma unroll
    for (int i = 0; i < 4; i++) {
        int m = m0 + ty * 4 + i;
        if (m >= M) continue;
#pragma unroll
        for (int j = 0; j < 4; j++) {
            int n = n0 + tx * 4 + j;
            if (n >= N) continue;
            float v = acc[i][j];
            if (bias)   v += bias[n];
            if (addend) v += addend[(size_t)m * ldadd + n];
            Cp[(size_t)m * ldc + n] = v;
        }
    }
}

// ---------------------------------------------------------------------------
// Small helper kernels
// ---------------------------------------------------------------------------
__global__ void wcat_fill(const float* __restrict__ sEmbed_w,
                          const float* __restrict__ sEmbed_b,
                          const float* __restrict__ w_hh,
                          const float* __restrict__ b_hh)
{
    int idx = blockIdx.x * blockDim.x + threadIdx.x;
    if (idx < 2048 * 512) {
        int n = idx >> 9;
        g_Wcat[idx] = (n < 512) ? sEmbed_w[idx] : w_hh[idx - 512 * 512];
    }
    if (idx < 2048)
        g_bcat[idx] = (idx < 512) ? sEmbed_b[idx] : b_hh[idx - 512];
}

__global__ void splitk_reduce(const float* __restrict__ bias)
{
    int idx = blockIdx.x * blockDim.x + threadIdx.x;   // 256*300
    if (idx >= 256 * 300) return;
    float s = 0.f;
#pragma unroll
    for (int z = 0; z < 16; z++) s += g_EbufPart[z * (256 * 300) + idx];
    g_emb[idx] = s + bias[idx % 300];
}

__global__ void yp_gather(const int* __restrict__ targets,
                          const float* __restrict__ tgt_emb)
{
    int idx = blockIdx.x * blockDim.x + threadIdx.x;   // 25*256*512
    if (idx >= TDEC * 256 * 512) return;
    int d = idx & 511;
    int row = idx >> 9;          // t*256 + b
    int b = row & 255;
    int t = row >> 8;
    int y = (t == 0) ? YDIM_ : targets[b * TDEC + (t - 1)];
    g_Yp[idx] = tgt_emb[(size_t)y * 512 + d];
}

// Fused attention with warp-shuffle reductions.
__global__ __launch_bounds__(256)
void attn_kernel(const float* __restrict__ x,
                 const float* __restrict__ wEmbed_w,
                 const float* __restrict__ wEmbed_b)
{
    int b = blockIdx.x;
    int tid = threadIdx.x;
    int lane = tid & 31, warp = tid >> 5;
    __shared__ float sP[512];
    __shared__ float wsum[8];
    __shared__ float alpha[32];

    sP[tid]       = g_C1[b * 2048 + tid];
    sP[tid + 256] = g_C1[b * 2048 + 256 + tid];
    float w0 = wEmbed_w[tid];
    float w1 = wEmbed_w[tid + 256];
    float wb = wEmbed_b[0];
    __syncthreads();

    for (int t = 0; t < TENC; t++) {
        const float* xp = g_XP + (size_t)(b * TENC + t) * 512;
        float v = w0 * tanhf(sP[tid] + xp[tid]) +
                  w1 * tanhf(sP[tid + 256] + xp[tid + 256]);
#pragma unroll
        for (int o = 16; o > 0; o >>= 1) v += __shfl_xor_sync(0xffffffffu, v, o);
        if (lane == 0) wsum[warp] = v;
        __syncthreads();
        if (warp == 0) {
            float s = (lane < 8) ? wsum[lane] : 0.f;
#pragma unroll
            for (int o = 4; o > 0; o >>= 1) s += __shfl_xor_sync(0xffffffffu, s, o);
            if (lane == 0) alpha[t] = s + wb;
        }
        __syncthreads();
    }

    if (tid < 32) {
        float ev = (tid < TENC) ? alpha[tid] : -1e30f;
        float m = ev;
#pragma unroll
        for (int o = 16; o > 0; o >>= 1) m = fmaxf(m, __shfl_xor_sync(0xffffffffu, m, o));
        float ex = (tid < TENC) ? __expf(ev - m) : 0.f;
        float s = ex;
#pragma unroll
        for (int o = 16; o > 0; o >>= 1) s += __shfl_xor_sync(0xffffffffu, s, o);
        if (tid < TENC) alpha[tid] = ex / s;
    }
    __syncthreads();

    float c0 = 0.f, c1 = 0.f;
#pragma unroll
    for (int t = 0; t < TENC; t++) {
        const float* xr = x + (size_t)(b * TENC + t) * 512;
        float a = alpha[t];
        c0 = fmaf(a, xr[tid], c0);
        c1 = fmaf(a, xr[tid + 256], c1);
    }
    g_ctx[b * 512 + tid] = c0;
    g_ctx[b * 512 + 256 + tid] = c1;
}

// ---------------------------------------------------------------------------
// Launch
// ---------------------------------------------------------------------------
extern "C" void kernel_launch(void* const* d_in, const int* in_sizes, int n_in,
                              void* d_out, int out_size)
{
    int off = (n_in > 19) ? 1 : 0;
    const float* x          = (const float*)d_in[0];
    const int*   targets    = (const int*)  d_in[1];
    const float* eEmbed_w   = (const float*)d_in[2 + off];
    const float* eEmbed_b   = (const float*)d_in[3 + off];
    const float* embed_fc_w = (const float*)d_in[4 + off];
    const float* embed_fc_b = (const float*)d_in[5 + off];
    const float* sEmbed_w   = (const float*)d_in[6 + off];
    const float* sEmbed_b   = (const float*)d_in[7 + off];
    const float* xEmbed_w   = (const float*)d_in[8 + off];
    const float* xEmbed_b   = (const float*)d_in[9 + off];
    const float* wEmbed_w   = (const float*)d_in[10 + off];
    const float* wEmbed_b   = (const float*)d_in[11 + off];
    const float* tgt_emb    = (const float*)d_in[12 + off];
    const float* gru_w_ih   = (const float*)d_in[13 + off];
    const float* gru_w_hh   = (const float*)d_in[14 + off];
    const float* gru_b_ih   = (const float*)d_in[15 + off];
    const float* gru_b_hh   = (const float*)d_in[16 + off];
    const float* fc_w       = (const float*)d_in[17 + off];
    const float* fc_b       = (const float*)d_in[18 + off];
    float* out = (float*)d_out;

    float *pWcat, *pbcat, *pEbufPart, *pemb, *pXP, *pYp, *pGIY, *pstates, *pctx, *pC1;
    cudaGetSymbolAddress((void**)&pWcat,     g_Wcat);
    cudaGetSymbolAddress((void**)&pbcat,     g_bcat);
    cudaGetSymbolAddress((void**)&pEbufPart, g_EbufPart);
    cudaGetSymbolAddress((void**)&pemb,      g_emb);
    cudaGetSymbolAddress((void**)&pXP,       g_XP);
    cudaGetSymbolAddress((void**)&pYp,       g_Yp);
    cudaGetSymbolAddress((void**)&pGIY,      g_GIY);
    cudaGetSymbolAddress((void**)&pstates,   g_states);
    cudaGetSymbolAddress((void**)&pctx,      g_ctx);
    cudaGetSymbolAddress((void**)&pC1,       g_C1);

    // ---- Prologue (loop-invariant work) ----
    wcat_fill<<<4096, 256>>>(sEmbed_w, sEmbed_b, gru_w_hh, gru_b_hh);

    // embed = x_flat @ eEmbed_w.T  (K=12800, split-K 16-way, fp32)
    sgemm64<<<dim3(5, 4, 16), 256>>>(x, TENC * XDIM_, eEmbed_w, TENC * XDIM_,
                                     nullptr, nullptr, 0,
                                     pEbufPart, 300, 256, 300, TENC * XDIM_, 800);
    splitk_reduce<<<300, 256>>>(eEmbed_b);

    // state0 = emb @ embed_fc_w.T  (K=300, fp32)
    sgemm64<<<dim3(8, 4), 256>>>(pemb, 300, embed_fc_w, 300, embed_fc_b,
                                 nullptr, 0, pstates, 512, 256, 512, 300, 0);

    // xProj = x @ xEmbed_w.T  (TF32 pipelined)
    wgemm<<<dim3(4, 50), 256>>>(x, 512, xEmbed_w, 512, xEmbed_b,
                                pXP, 512, 6400, 512, 512, 0);

    // yProj gather, then GIY = Yp @ w_ih[:, :512].T + b_ih (TF32 pipelined)
    yp_gather<<<12800, 256>>>(targets, tgt_emb);
    wgemm<<<dim3(12, 50), 256>>>(pYp, 512, gru_w_ih, 1024, gru_b_ih,
                                 pGIY, 1536, 6400, 1536, 512, 0);

    // ---- Sequential decode loop (TF32 tensor cores, 3 kernels/step) ----
    for (int t = 0; t < TDEC; t++) {
        const float* state_in = pstates + (size_t)t * (256 * 512);
        float* state_out      = pstates + (size_t)(t + 1) * (256 * 512);

        // [sProj | gh] = state @ [sEmbed_w ; w_hh].T   (256 x 2048 x 512)
        wgemm_small<<<dim3(32, 4), 128>>>(state_in, 512, pWcat, 512, pbcat,
                                          pC1, 2048, 512);

        // attention -> context
        attn_kernel<<<256, 256>>>(x, wEmbed_w, wEmbed_b);

        // fused: gi slices + GRU gates -> states[t+1]
        gi3_gru<<<dim3(8, 4), 128>>>(pctx, gru_w_ih + 512,
                                     pGIY + (size_t)t * (256 * 1536),
                                     state_in, state_out);
    }

    // ---- Epilogue: batched fc over all 25 states (TF32 pipelined) ----
    wgemm<<<dim3(52, 50), 256>>>(pstates + 256 * 512, 512, fc_w, 512, fc_b,
                                 out, 0, 6400, YDIM_, 512, 1);
}

// round 11
// speedup vs baseline: 1.6938x; 1.6938x over previous
#include <cstdint>
#include <cuda_runtime.h>
#include <cuda_bf16.h>
#include <mma.h>

using namespace nvcuda;

// Problem constants
#define BB      256
#define TENC    25
#define XDIM_   512
#define SDIM_   512
#define ADIM_   512
#define YDIM_   6625
#define TDEC    25
#define EMBIN   300

// ---------------------------------------------------------------------------
// Static device scratch
// ---------------------------------------------------------------------------
__device__ __align__(256) float g_Wcat[2048 * 512];      // [sEmbed_w ; gru_w_hh]
__device__ __align__(256) float g_bcat[2048];
__device__ __align__(256) float g_EbufPart[16 * 256 * 300];
__device__ __align__(256) float g_emb[256 * 300];
__device__ __align__(256) float g_XP[6400 * 512];        // xProj, row = b*25+t
__device__ __align__(256) float g_Yp[6400 * 512];        // yProj, row = t*256+b
__device__ __align__(256) float g_GIY[6400 * 1536];      // precomputed gi (yProj part + b_ih)
__device__ __align__(256) float g_states[26 * 256 * 512];// state0 .. state25
__device__ __align__(256) float g_C1[256 * 2048];        // [sProj | gh] per step
__device__ __align__(256) float g_GI[256 * 1536];        // gi per step
__device__ __align__(256) float g_ctx[256 * 512];        // attention context

// ---------------------------------------------------------------------------
// cp.async helpers
// ---------------------------------------------------------------------------
__device__ __forceinline__ void cp_async16(void* smem_dst, const void* gptr, bool pred)
{
    unsigned int sa = (unsigned int)__cvta_generic_to_shared(smem_dst);
    int bytes = pred ? 16 : 0;
    asm volatile("cp.async.ca.shared.global [%0], [%1], 16, %2;\n"
                 :: "r"(sa), "l"(gptr), "r"(bytes));
}

// ---------------------------------------------------------------------------
// Pipelined TF32 wmma GEMM (NT): C = A @ W^T + bias. Block 128x128, BK=16,
// 2-stage cp.async double buffering, 8 warps (2x4), warp tile 64x32.
// Bias folded into accumulator init. Direct fragment stores for the
// non-permuted interior path (even ldc => 8B-aligned v2 stores). The permuted
// fc output has odd row stride so it uses the staged scalar-store path.
// Requires M % 128 == 0, K % 16 == 0.
// ---------------------------------------------------------------------------
__global__ __launch_bounds__(256)
void wgemm(const float* __restrict__ A, int lda,
           const float* __restrict__ W, int ldw,
           const float* __restrict__ bias,
           float* __restrict__ C, int ldc,
           int M, int N, int K, int permuted)
{
    __shared__ float sm[10240];     // 40 KB
    const int LDS = 20;
    // stage s: A at s*5120, W at s*5120 + 2560  ([128][20] each)

    int tid  = threadIdx.x;
    int warp = tid >> 5;
    int wr   = warp >> 2;           // 0..1
    int wc   = warp & 3;            // 0..3
    int m0 = blockIdx.y * 128;
    int n0 = blockIdx.x * 128;

    // ---- bias -> accumulator init (broadcast tile in smem) ----
    {
        float* Bs = sm;             // [16][136]
        const int LDB = 136;
        for (int i = tid; i < 16 * 128; i += 256) {
            int r = i >> 7, c = i & 127;
            int n = n0 + c;
            Bs[r * LDB + c] = (bias && n < N) ? bias[n] : 0.f;
        }
        __syncthreads();
    }
    wmma::fragment<wmma::accumulator, 16, 16, 8, float> c_frag[4][2];
    {
        float* Bs = sm;
        const int LDB = 136;
#pragma unroll
        for (int j = 0; j < 2; j++) {
            wmma::load_matrix_sync(c_frag[0][j], &Bs[wc * 32 + j * 16], LDB, wmma::mem_row_major);
#pragma unroll
            for (int i = 1; i < 4; i++)
#pragma unroll
                for (int t = 0; t < c_frag[0][j].num_elements; t++)
                    c_frag[i][j].x[t] = c_frag[0][j].x[t];
        }
        __syncthreads();
    }

    int nIter = K >> 4;

    auto load_stage = [&](int k0, int s) {
        float* As = sm + s * 5120;
        float* Ws = sm + s * 5120 + 2560;
#pragma unroll
        for (int i = 0; i < 2; i++) {
            int idx = tid + i * 256;
            int r  = idx >> 2;
            int c4 = (idx & 3) * 4;
            cp_async16(&As[r * LDS + c4], &A[(size_t)(m0 + r) * lda + k0 + c4], true);
            int gn = n0 + r;
            cp_async16(&Ws[r * LDS + c4], &W[(size_t)gn * ldw + k0 + c4], gn < N);
        }
        asm volatile("cp.async.commit_group;\n");
    };

    load_stage(0, 0);

    for (int it = 0; it < nIter; it++) {
        if (it + 1 < nIter) {
            load_stage((it + 1) << 4, (it + 1) & 1);
            asm volatile("cp.async.wait_group 1;\n");
        } else {
            asm volatile("cp.async.wait_group 0;\n");
        }
        __syncthreads();

        float* As = sm + (it & 1) * 5120;
        float* Ws = sm + (it & 1) * 5120 + 2560;
#pragma unroll
        for (int ks = 0; ks < 16; ks += 8) {
            wmma::fragment<wmma::matrix_a, 16, 16, 8, wmma::precision::tf32, wmma::row_major> a_frag[4];
            wmma::fragment<wmma::matrix_b, 16, 16, 8, wmma::precision::tf32, wmma::col_major> b_frag[2];
#pragma unroll
            for (int i = 0; i < 4; i++) {
                wmma::load_matrix_sync(a_frag[i], &As[(wr * 64 + i * 16) * LDS + ks], LDS);
#pragma unroll
                for (int t = 0; t < a_frag[i].num_elements; t++)
                    a_frag[i].x[t] = wmma::__float_to_tf32(a_frag[i].x[t]);
            }
#pragma unroll
            for (int j = 0; j < 2; j++) {
                wmma::load_matrix_sync(b_frag[j], &Ws[(wc * 32 + j * 16) * LDS + ks], LDS);
#pragma unroll
                for (int t = 0; t < b_frag[j].num_elements; t++)
                    b_frag[j].x[t] = wmma::__float_to_tf32(b_frag[j].x[t]);
            }
#pragma unroll
            for (int i = 0; i < 4; i++)
#pragma unroll
                for (int j = 0; j < 2; j++)
                    wmma::mma_sync(c_frag[i][j], a_frag[i], b_frag[j], c_frag[i][j]);
        }
        __syncthreads();
    }

    if (!permuted && n0 + 128 <= N) {
        // Fast path: direct fragment stores to global (even ldc, 8B-aligned).
#pragma unroll
        for (int i = 0; i < 4; i++) {
            int m = m0 + wr * 64 + i * 16;
#pragma unroll
            for (int j = 0; j < 2; j++) {
                int n = n0 + wc * 32 + j * 16;
                wmma::store_matrix_sync(&C[(size_t)m * ldc + n],
                                        c_frag[i][j], ldc, wmma::mem_row_major);
            }
        }
    } else {
        // Staged path: shared staging + guarded scalar writes (alignment-safe).
        float* Cs = sm;             // [64][132]
        const int LDCS = 132;
#pragma unroll
        for (int p = 0; p < 2; p++) {
            if (wr == p) {
#pragma unroll
                for (int i = 0; i < 4; i++)
#pragma unroll
                    for (int j = 0; j < 2; j++)
                        wmma::store_matrix_sync(&Cs[(i * 16) * LDCS + wc * 32 + j * 16],
                                                c_frag[i][j], LDCS, wmma::mem_row_major);
            }
            __syncthreads();
#pragma unroll
            for (int i = 0; i < 32; i++) {
                int idx = tid + i * 256;
                int r = idx >> 7;
                int c = idx & 127;
                int m = m0 + p * 64 + r;
                int n = n0 + c;
                if (n < N) {
                    float v = Cs[r * LDCS + c];
                    if (permuted) {
                        int b = m & 255;
                        int t = m >> 8;
                        C[(size_t)b * (TDEC * YDIM_) + (size_t)t * YDIM_ + n] = v;
                    } else {
                        C[(size_t)m * ldc + n] = v;
                    }
                }
            }
            __syncthreads();
        }
    }
}

// ---------------------------------------------------------------------------
// Small TF32 wmma GEMM (NT) for the decode loop: block 64x64, 4 warps (2x2),
// warp tile 32x32, BK=32. C = A @ W^T (+bias[n]) (+addend[m][n]).
// ---------------------------------------------------------------------------
__global__ __launch_bounds__(128)
void wgemm_small(const float* __restrict__ A, int lda,
                 const float* __restrict__ W, int ldw,
                 const float* __restrict__ bias,
                 const float* __restrict__ addend, int ldadd,
                 float* __restrict__ C, int ldc, int K)
{
    __shared__ float sm[4608];
    const int LDS = 36;
    float* As = sm;                 // [64][36]
    float* Ws = sm + 2304;

    int tid  = threadIdx.x;
    int warp = tid >> 5;
    int wr   = warp >> 1;           // 0..1
    int wc   = warp & 1;            // 0..1
    int m0 = blockIdx.y * 64;
    int n0 = blockIdx.x * 64;

    wmma::fragment<wmma::accumulator, 16, 16, 8, float> c_frag[2][2];
#pragma unroll
    for (int i = 0; i < 2; i++)
#pragma unroll
        for (int j = 0; j < 2; j++)
            wmma::fill_fragment(c_frag[i][j], 0.0f);

    for (int k0 = 0; k0 < K; k0 += 32) {
#pragma unroll
        for (int i = 0; i < 4; i++) {
            int idx = tid + i * 128;        // 0..511
            int r  = idx >> 3;              // 0..63
            int c4 = (idx & 7) * 4;         // 0..28
            *(float4*)&As[r * LDS + c4] = *(const float4*)&A[(size_t)(m0 + r) * lda + k0 + c4];
            *(float4*)&Ws[r * LDS + c4] = *(const float4*)&W[(size_t)(n0 + r) * ldw + k0 + c4];
        }
        __syncthreads();
#pragma unroll
        for (int ks = 0; ks < 32; ks += 8) {
            wmma::fragment<wmma::matrix_a, 16, 16, 8, wmma::precision::tf32, wmma::row_major> a_frag[2];
            wmma::fragment<wmma::matrix_b, 16, 16, 8, wmma::precision::tf32, wmma::col_major> b_frag[2];
#pragma unroll
            for (int i = 0; i < 2; i++) {
                wmma::load_matrix_sync(a_frag[i], &As[(wr * 32 + i * 16) * LDS + ks], LDS);
#pragma unroll
                for (int t = 0; t < a_frag[i].num_elements; t++)
                    a_frag[i].x[t] = wmma::__float_to_tf32(a_frag[i].x[t]);
            }
#pragma unroll
            for (int j = 0; j < 2; j++) {
                wmma::load_matrix_sync(b_frag[j], &Ws[(wc * 32 + j * 16) * LDS + ks], LDS);
#pragma unroll
                for (int t = 0; t < b_frag[j].num_elements; t++)
                    b_frag[j].x[t] = wmma::__float_to_tf32(b_frag[j].x[t]);
            }
#pragma unroll
            for (int i = 0; i < 2; i++)
#pragma unroll
                for (int j = 0; j < 2; j++)
                    wmma::mma_sync(c_frag[i][j], a_frag[i], b_frag[j], c_frag[i][j]);
        }
        __syncthreads();
    }

    // Epilogue via shared staging
    float* Cs = sm;                 // [64][68]
    const int LDCS = 68;
#pragma unroll
    for (int i = 0; i < 2; i++)
#pragma unroll
        for (int j = 0; j < 2; j++)
            wmma::store_matrix_sync(&Cs[(wr * 32 + i * 16) * LDCS + wc * 32 + j * 16],
                                    c_frag[i][j], LDCS, wmma::mem_row_major);
    __syncthreads();
#pragma unroll
    for (int i = 0; i < 32; i++) {
        int idx = tid + i * 128;            // 0..4095
        int r = idx >> 6;
        int c = idx & 63;
        int m = m0 + r, n = n0 + c;
        float v = Cs[r * LDCS + c];
        if (bias)   v += bias[n];
        if (addend) v += addend[(size_t)m * ldadd + n];
        C[(size_t)m * ldc + n] = v;
    }
}

// ---------------------------------------------------------------------------
// fp32 SGEMM 64x64 (prologue only: embed split-K, state0)
// ---------------------------------------------------------------------------
__global__ __launch_bounds__(256)
void sgemm64(const float* __restrict__ A, int lda,
             const float* __restrict__ W, int ldw,
             const float* __restrict__ bias,
             const float* __restrict__ addend, int ldadd,
             float* __restrict__ C, int ldc,
             int M, int N, int K, int Kc)
{
    __shared__ float As[16][68];
    __shared__ float Ws[16][68];

    int tid = threadIdx.x;
    int tx = tid & 15, ty = tid >> 4;
    int m0 = blockIdx.y * 64, n0 = blockIdx.x * 64;

    int kstart = 0, kend = K;
    float* Cp = C;
    if (Kc > 0) {
        kstart = blockIdx.z * Kc;
        kend = min(K, kstart + Kc);
        Cp = C + (size_t)blockIdx.z * (size_t)M * (size_t)ldc;
    }

    float acc[4][4];
#pragma unroll
    for (int i = 0; i < 4; i++)
#pragma unroll
        for (int j = 0; j < 4; j++) acc[i][j] = 0.f;

    for (int k0 = kstart; k0 < kend; k0 += 16) {
#pragma unroll
        for (int i = 0; i < 4; i++) {
            int idx = tid + i * 256;
            int r = idx >> 4, kk = idx & 15;
            int gk = k0 + kk;
            int gm = m0 + r;
            As[kk][r] = (gm < M && gk < kend) ? A[(size_t)gm * lda + gk] : 0.f;
            int gn = n0 + r;
            Ws[kk][r] = (gn < N && gk < kend) ? W[(size_t)gn * ldw + gk] : 0.f;
        }
        __syncthreads();
#pragma unroll
        for (int kk = 0; kk < 16; kk++) {
            float4 a = *(const float4*)&As[kk][ty * 4];
            float4 b = *(const float4*)&Ws[kk][tx * 4];
            float av[4] = {a.x, a.y, a.z, a.w};
            float bv[4] = {b.x, b.y, b.z, b.w};
#pragma unroll
            for (int i = 0; i < 4; i++)
#pragma unroll
                for (int j = 0; j < 4; j++)
                    acc[i][j] = fmaf(av[i], bv[j], acc[i][j]);
        }
        __syncthreads();
    }

#pragma unroll
    for (int i = 0; i < 4; i++) {
        int m = m0 + ty * 4 + i;
        if (m >= M) continue;
#pragma unroll
        for (int j = 0; j < 4; j++) {
            int n = n0 + tx * 4 + j;
            if (n >= N) continue;
            float v = acc[i][j];
            if (bias)   v += bias[n];
            if (addend) v += addend[(size_t)m * ldadd + n];
            Cp[(size_t)m * ldc + n] = v;
        }
    }
}

// ---------------------------------------------------------------------------
// Small helper kernels
// ---------------------------------------------------------------------------
__global__ void wcat_fill(const float* __restrict__ sEmbed_w,
                          const float* __restrict__ sEmbed_b,
                          const float* __restrict__ w_hh,
                          const float* __restrict__ b_hh)
{
    int idx = blockIdx.x * blockDim.x + threadIdx.x;
    if (idx < 2048 * 512) {
        int n = idx >> 9;
        g_Wcat[idx] = (n < 512) ? sEmbed_w[idx] : w_hh[idx - 512 * 512];
    }
    if (idx < 2048)
        g_bcat[idx] = (idx < 512) ? sEmbed_b[idx] : b_hh[idx - 512];
}

__global__ void splitk_reduce(const float* __restrict__ bias)
{
    int idx = blockIdx.x * blockDim.x + threadIdx.x;   // 256*300
    if (idx >= 256 * 300) return;
    float s = 0.f;
#pragma unroll
    for (int z = 0; z < 16; z++) s += g_EbufPart[z * (256 * 300) + idx];
    g_emb[idx] = s + bias[idx % 300];
}

__global__ void yp_gather(const int* __restrict__ targets,
                          const float* __restrict__ tgt_emb)
{
    int idx = blockIdx.x * blockDim.x + threadIdx.x;   // 25*256*512
    if (idx >= TDEC * 256 * 512) return;
    int d = idx & 511;
    int row = idx >> 9;          // t*256 + b
    int b = row & 255;
    int t = row >> 8;
    int y = (t == 0) ? YDIM_ : targets[b * TDEC + (t - 1)];
    g_Yp[idx] = tgt_emb[(size_t)y * 512 + d];
}

// Fused attention with warp-shuffle reductions.
__global__ __launch_bounds__(256)
void attn_kernel(const float* __restrict__ x,
                 const float* __restrict__ wEmbed_w,
                 const float* __restrict__ wEmbed_b)
{
    int b = blockIdx.x;
    int tid = threadIdx.x;
    int lane = tid & 31, warp = tid >> 5;
    __shared__ float sP[512];
    __shared__ float wsum[8];
    __shared__ float alpha[32];

    sP[tid]       = g_C1[b * 2048 + tid];
    sP[tid + 256] = g_C1[b * 2048 + 256 + tid];
    float w0 = wEmbed_w[tid];
    float w1 = wEmbed_w[tid + 256];
    float wb = wEmbed_b[0];
    __syncthreads();

    for (int t = 0; t < TENC; t++) {
        const float* xp = g_XP + (size_t)(b * TENC + t) * 512;
        float v = w0 * tanhf(sP[tid] + xp[tid]) +
                  w1 * tanhf(sP[tid + 256] + xp[tid + 256]);
#pragma unroll
        for (int o = 16; o > 0; o >>= 1) v += __shfl_xor_sync(0xffffffffu, v, o);
        if (lane == 0) wsum[warp] = v;
        __syncthreads();
        if (warp == 0) {
            float s = (lane < 8) ? wsum[lane] : 0.f;
#pragma unroll
            for (int o = 4; o > 0; o >>= 1) s += __shfl_xor_sync(0xffffffffu, s, o);
            if (lane == 0) alpha[t] = s + wb;
        }
        __syncthreads();
    }

    if (tid < 32) {
        float ev = (tid < TENC) ? alpha[tid] : -1e30f;
        float m = ev;
#pragma unroll
        for (int o = 16; o > 0; o >>= 1) m = fmaxf(m, __shfl_xor_sync(0xffffffffu, m, o));
        float ex = (tid < TENC) ? __expf(ev - m) : 0.f;
        float s = ex;
#pragma unroll
        for (int o = 16; o > 0; o >>= 1) s += __shfl_xor_sync(0xffffffffu, s, o);
        if (tid < TENC) alpha[tid] = ex / s;
    }
    __syncthreads();

    float c0 = 0.f, c1 = 0.f;
#pragma unroll
    for (int t = 0; t < TENC; t++) {
        const float* xr = x + (size_t)(b * TENC + t) * 512;
        float a = alpha[t];
        c0 = fmaf(a, xr[tid], c0);
        c1 = fmaf(a, xr[tid + 256], c1);
    }
    g_ctx[b * 512 + tid] = c0;
    g_ctx[b * 512 + 256 + tid] = c1;
}

// GRU gate fusion: reads g_GI (gi) and g_C1 (gh in cols 512..2047), updates state.
__global__ void gru_fuse(int t)
{
    int idx = blockIdx.x * blockDim.x + threadIdx.x;   // 256*512
    if (idx >= 256 * 512) return;
    int b = idx >> 9, j = idx & 511;
    const float* gi = g_GI + b * 1536;
    const float* gh = g_C1 + b * 2048 + 512;
    float ir = gi[j],        iz = gi[512 + j],  in_ = gi[1024 + j];
    float hr = gh[j],        hz = gh[512 + j],  hn  = gh[1024 + j];
    float r = 1.f / (1.f + __expf(-(ir + hr)));
    float z = 1.f / (1.f + __expf(-(iz + hz)));
    float n = tanhf(in_ + r * hn);
    const float* s_in  = g_states + (size_t)t * (256 * 512);
    float*       s_out = g_states + (size_t)(t + 1) * (256 * 512);
    s_out[idx] = (1.f - z) * n + z * s_in[idx];
}

// ---------------------------------------------------------------------------
// Launch
// ---------------------------------------------------------------------------
extern "C" void kernel_launch(void* const* d_in, const int* in_sizes, int n_in,
                              void* d_out, int out_size)
{
    int off = (n_in > 19) ? 1 : 0;
    const float* x          = (const float*)d_in[0];
    const int*   targets    = (const int*)  d_in[1];
    const float* eEmbed_w   = (const float*)d_in[2 + off];
    const float* eEmbed_b   = (const float*)d_in[3 + off];
    const float* embed_fc_w = (const float*)d_in[4 + off];
    const float* embed_fc_b = (const float*)d_in[5 + off];
    const float* sEmbed_w   = (const float*)d_in[6 + off];
    const float* sEmbed_b   = (const float*)d_in[7 + off];
    const float* xEmbed_w   = (const float*)d_in[8 + off];
    const float* xEmbed_b   = (const float*)d_in[9 + off];
    const float* wEmbed_w   = (const float*)d_in[10 + off];
    const float* wEmbed_b   = (const float*)d_in[11 + off];
    const float* tgt_emb    = (const float*)d_in[12 + off];
    const float* gru_w_ih   = (const float*)d_in[13 + off];
    const float* gru_w_hh   = (const float*)d_in[14 + off];
    const float* gru_b_ih   = (const float*)d_in[15 + off];
    const float* gru_b_hh   = (const float*)d_in[16 + off];
    const float* fc_w       = (const float*)d_in[17 + off];
    const float* fc_b       = (const float*)d_in[18 + off];
    float* out = (float*)d_out;

    float *pWcat, *pbcat, *pEbufPart, *pemb, *pXP, *pYp, *pGIY, *pstates, *pC1, *pGI, *pctx;
    cudaGetSymbolAddress((void**)&pWcat,     g_Wcat);
    cudaGetSymbolAddress((void**)&pbcat,     g_bcat);
    cudaGetSymbolAddress((void**)&pEbufPart, g_EbufPart);
    cudaGetSymbolAddress((void**)&pemb,      g_emb);
    cudaGetSymbolAddress((void**)&pXP,       g_XP);
    cudaGetSymbolAddress((void**)&pYp,       g_Yp);
    cudaGetSymbolAddress((void**)&pGIY,      g_GIY);
    cudaGetSymbolAddress((void**)&pstates,   g_states);
    cudaGetSymbolAddress((void**)&pC1,       g_C1);
    cudaGetSymbolAddress((void**)&pGI,       g_GI);
    cudaGetSymbolAddress((void**)&pctx,      g_ctx);

    // ---- Prologue (loop-invariant work) ----
    wcat_fill<<<4096, 256>>>(sEmbed_w, sEmbed_b, gru_w_hh, gru_b_hh);

    // embed = x_flat @ eEmbed_w.T  (K=12800, split-K 16-way, fp32)
    sgemm64<<<dim3(5, 4, 16), 256>>>(x, TENC * XDIM_, eEmbed_w, TENC * XDIM_,
                                     nullptr, nullptr, 0,
                                     pEbufPart, 300, 256, 300, TENC * XDIM_, 800);
    splitk_reduce<<<300, 256>>>(eEmbed_b);

    // state0 = emb @ embed_fc_w.T  (K=300, fp32)
    sgemm64<<<dim3(8, 4), 256>>>(pemb, 300, embed_fc_w, 300, embed_fc_b,
                                 nullptr, 0, pstates, 512, 256, 512, 300, 0);

    // xProj = x @ xEmbed_w.T  (TF32 pipelined, direct-store fast path)
    wgemm<<<dim3(4, 50), 256>>>(x, 512, xEmbed_w, 512, xEmbed_b,
                                pXP, 512, 6400, 512, 512, 0);

    // yProj gather, then GIY = Yp @ w_ih[:, :512].T + b_ih (TF32 pipelined)
    yp_gather<<<12800, 256>>>(targets, tgt_emb);
    wgemm<<<dim3(12, 50), 256>>>(pYp, 512, gru_w_ih, 1024, gru_b_ih,
                                 pGIY, 1536, 6400, 1536, 512, 0);

    // ---- Sequential decode loop (TF32 tensor cores, round-8 structure) ----
    for (int t = 0; t < TDEC; t++) {
        const float* state_in = pstates + (size_t)t * (256 * 512);

        // [sProj | gh] = state @ [sEmbed_w ; w_hh].T   (256 x 2048 x 512)
        wgemm_small<<<dim3(32, 4), 128>>>(state_in, 512, pWcat, 512, pbcat,
                                          nullptr, 0, pC1, 2048, 512);

        // attention -> context
        attn_kernel<<<256, 256>>>(x, wEmbed_w, wEmbed_b);

        // gi = GIY[t] + context @ w_ih[:, 512:1024].T  (256 x 1536 x 512)
        wgemm_small<<<dim3(24, 4), 128>>>(pctx, 512, gru_w_ih + 512, 1024, nullptr,
                                          pGIY + (size_t)t * (256 * 1536), 1536,
                                          pGI, 1536, 512);

        // GRU gates -> states[t+1]
        gru_fuse<<<512, 256>>>(t);
    }

    // ---- Epilogue: batched fc over all 25 states (TF32 pipelined, staged) ----
    wgemm<<<dim3(52, 50), 256>>>(pstates + 256 * 512, 512, fc_w, 512, fc_b,
                                 out, 0, 6400, YDIM_, 512, 1);
}

// round 12
// speedup vs baseline: 2.1277x; 1.2562x over previous
#include <cstdint>
#include <cuda_runtime.h>
#include <cuda_bf16.h>
#include <mma.h>

using namespace nvcuda;

// Problem constants
#define BB      256
#define TENC    25
#define XDIM_   512
#define SDIM_   512
#define ADIM_   512
#define YDIM_   6625
#define TDEC    25
#define EMBIN   300

// ---------------------------------------------------------------------------
// Static device scratch
// ---------------------------------------------------------------------------
__device__ __align__(256) float g_Wcat[2048 * 512];      // [sEmbed_w ; gru_w_hh]
__device__ __align__(256) float g_bcat[2048];
__device__ __align__(256) float g_EbufPart[16 * 256 * 300];
__device__ __align__(256) float g_emb[256 * 300];
__device__ __align__(256) float g_XP[6400 * 512];        // xProj, row = b*25+t
__device__ __align__(256) float g_Yp[6400 * 512];        // yProj, row = t*256+b
__device__ __align__(256) float g_GIY[6400 * 1536];      // precomputed gi (yProj part + b_ih)
__device__ __align__(256) float g_states[26 * 256 * 512];// state0 .. state25
__device__ __align__(256) float g_C1[256 * 2048];        // [sProj | gh] per step
__device__ __align__(256) float g_GI[256 * 1536];        // gi per step
__device__ __align__(256) float g_ctx[256 * 512];        // attention context

// ---------------------------------------------------------------------------
// cp.async helpers
// ---------------------------------------------------------------------------
__device__ __forceinline__ void cp_async16(void* smem_dst, const void* gptr, bool pred)
{
    unsigned int sa = (unsigned int)__cvta_generic_to_shared(smem_dst);
    int bytes = pred ? 16 : 0;
    asm volatile("cp.async.ca.shared.global [%0], [%1], 16, %2;\n"
                 :: "r"(sa), "l"(gptr), "r"(bytes));
}

// ---------------------------------------------------------------------------
// Pipelined TF32 wmma GEMM (NT): C = A @ W^T + bias. Block 128x128, BK=16,
// 2-stage cp.async double buffering, 8 warps (2x4), warp tile 64x32.
// Bias folded into accumulator init. Direct fragment stores for the
// non-permuted interior path (even ldc => 8B-aligned v2 stores). The permuted
// fc output has odd row stride so it uses the staged scalar-store path.
// Requires M % 128 == 0, K % 16 == 0.
// ---------------------------------------------------------------------------
__global__ __launch_bounds__(256)
void wgemm(const float* __restrict__ A, int lda,
           const float* __restrict__ W, int ldw,
           const float* __restrict__ bias,
           float* __restrict__ C, int ldc,
           int M, int N, int K, int permuted)
{
    __shared__ float sm[10240];     // 40 KB
    const int LDS = 20;
    // stage s: A at s*5120, W at s*5120 + 2560  ([128][20] each)

    int tid  = threadIdx.x;
    int warp = tid >> 5;
    int wr   = warp >> 2;           // 0..1
    int wc   = warp & 3;            // 0..3
    int m0 = blockIdx.y * 128;
    int n0 = blockIdx.x * 128;

    // ---- bias -> accumulator init (broadcast tile in smem) ----
    {
        float* Bs = sm;             // [16][136]
        const int LDB = 136;
        for (int i = tid; i < 16 * 128; i += 256) {
            int r = i >> 7, c = i & 127;
            int n = n0 + c;
            Bs[r * LDB + c] = (bias && n < N) ? bias[n] : 0.f;
        }
        __syncthreads();
    }
    wmma::fragment<wmma::accumulator, 16, 16, 8, float> c_frag[4][2];
    {
        float* Bs = sm;
        const int LDB = 136;
#pragma unroll
        for (int j = 0; j < 2; j++) {
            wmma::load_matrix_sync(c_frag[0][j], &Bs[wc * 32 + j * 16], LDB, wmma::mem_row_major);
#pragma unroll
            for (int i = 1; i < 4; i++)
#pragma unroll
                for (int t = 0; t < c_frag[0][j].num_elements; t++)
                    c_frag[i][j].x[t] = c_frag[0][j].x[t];
        }
        __syncthreads();
    }

    int nIter = K >> 4;

    auto load_stage = [&](int k0, int s) {
        float* As = sm + s * 5120;
        float* Ws = sm + s * 5120 + 2560;
#pragma unroll
        for (int i = 0; i < 2; i++) {
            int idx = tid + i * 256;
            int r  = idx >> 2;
            int c4 = (idx & 3) * 4;
            cp_async16(&As[r * LDS + c4], &A[(size_t)(m0 + r) * lda + k0 + c4], true);
            int gn = n0 + r;
            cp_async16(&Ws[r * LDS + c4], &W[(size_t)gn * ldw + k0 + c4], gn < N);
        }
        asm volatile("cp.async.commit_group;\n");
    };

    load_stage(0, 0);

    for (int it = 0; it < nIter; it++) {
        if (it + 1 < nIter) {
            load_stage((it + 1) << 4, (it + 1) & 1);
            asm volatile("cp.async.wait_group 1;\n");
        } else {
            asm volatile("cp.async.wait_group 0;\n");
        }
        __syncthreads();

        float* As = sm + (it & 1) * 5120;
        float* Ws = sm + (it & 1) * 5120 + 2560;
#pragma unroll
        for (int ks = 0; ks < 16; ks += 8) {
            wmma::fragment<wmma::matrix_a, 16, 16, 8, wmma::precision::tf32, wmma::row_major> a_frag[4];
            wmma::fragment<wmma::matrix_b, 16, 16, 8, wmma::precision::tf32, wmma::col_major> b_frag[2];
#pragma unroll
            for (int i = 0; i < 4; i++) {
                wmma::load_matrix_sync(a_frag[i], &As[(wr * 64 + i * 16) * LDS + ks], LDS);
#pragma unroll
                for (int t = 0; t < a_frag[i].num_elements; t++)
                    a_frag[i].x[t] = wmma::__float_to_tf32(a_frag[i].x[t]);
            }
#pragma unroll
            for (int j = 0; j < 2; j++) {
                wmma::load_matrix_sync(b_frag[j], &Ws[(wc * 32 + j * 16) * LDS + ks], LDS);
#pragma unroll
                for (int t = 0; t < b_frag[j].num_elements; t++)
                    b_frag[j].x[t] = wmma::__float_to_tf32(b_frag[j].x[t]);
            }
#pragma unroll
            for (int i = 0; i < 4; i++)
#pragma unroll
                for (int j = 0; j < 2; j++)
                    wmma::mma_sync(c_frag[i][j], a_frag[i], b_frag[j], c_frag[i][j]);
        }
        __syncthreads();
    }

    if (!permuted && n0 + 128 <= N) {
        // Fast path: direct fragment stores to global (even ldc, 8B-aligned).
#pragma unroll
        for (int i = 0; i < 4; i++) {
            int m = m0 + wr * 64 + i * 16;
#pragma unroll
            for (int j = 0; j < 2; j++) {
                int n = n0 + wc * 32 + j * 16;
                wmma::store_matrix_sync(&C[(size_t)m * ldc + n],
                                        c_frag[i][j], ldc, wmma::mem_row_major);
            }
        }
    } else {
        // Staged path: shared staging + guarded scalar writes (alignment-safe).
        float* Cs = sm;             // [64][132]
        const int LDCS = 132;
#pragma unroll
        for (int p = 0; p < 2; p++) {
            if (wr == p) {
#pragma unroll
                for (int i = 0; i < 4; i++)
#pragma unroll
                    for (int j = 0; j < 2; j++)
                        wmma::store_matrix_sync(&Cs[(i * 16) * LDCS + wc * 32 + j * 16],
                                                c_frag[i][j], LDCS, wmma::mem_row_major);
            }
            __syncthreads();
#pragma unroll
            for (int i = 0; i < 32; i++) {
                int idx = tid + i * 256;
                int r = idx >> 7;
                int c = idx & 127;
                int m = m0 + p * 64 + r;
                int n = n0 + c;
                if (n < N) {
                    float v = Cs[r * LDCS + c];
                    if (permuted) {
                        int b = m & 255;
                        int t = m >> 8;
                        C[(size_t)b * (TDEC * YDIM_) + (size_t)t * YDIM_ + n] = v;
                    } else {
                        C[(size_t)m * ldc + n] = v;
                    }
                }
            }
            __syncthreads();
        }
    }
}

// ---------------------------------------------------------------------------
// Small TF32 wmma GEMM (NT) for the decode loop: block 64x64, 4 warps (2x2),
// warp tile 32x32, BK=32 with 2-stage cp.async double buffering.
// C = A @ W^T (+bias[n]) (+addend[m][n]).
// Requires M%64==0, N%64==0, K%32==0 (all satisfied in the loop).
// ---------------------------------------------------------------------------
__global__ __launch_bounds__(128)
void wgemm_small(const float* __restrict__ A, int lda,
                 const float* __restrict__ W, int ldw,
                 const float* __restrict__ bias,
                 const float* __restrict__ addend, int ldadd,
                 float* __restrict__ C, int ldc, int K)
{
    __shared__ float sm[10240];     // 40 KB: stage s at s*5120 (A), +2560 (W)
    const int LDS = 40;             // 160B rows -> 16B-aligned cp.async dsts

    int tid  = threadIdx.x;
    int warp = tid >> 5;
    int wr   = warp >> 1;           // 0..1
    int wc   = warp & 1;            // 0..1
    int m0 = blockIdx.y * 64;
    int n0 = blockIdx.x * 64;

    wmma::fragment<wmma::accumulator, 16, 16, 8, float> c_frag[2][2];
#pragma unroll
    for (int i = 0; i < 2; i++)
#pragma unroll
        for (int j = 0; j < 2; j++)
            wmma::fill_fragment(c_frag[i][j], 0.0f);

    int nIter = K >> 5;

    auto load_stage = [&](int k0, int s) {
        float* As = sm + s * 5120;
        float* Ws = sm + s * 5120 + 2560;
#pragma unroll
        for (int i = 0; i < 4; i++) {
            int idx = tid + i * 128;        // 0..511
            int r  = idx >> 3;              // 0..63
            int c4 = (idx & 7) * 4;         // 0..28
            cp_async16(&As[r * LDS + c4], &A[(size_t)(m0 + r) * lda + k0 + c4], true);
            cp_async16(&Ws[r * LDS + c4], &W[(size_t)(n0 + r) * ldw + k0 + c4], true);
        }
        asm volatile("cp.async.commit_group;\n");
    };

    load_stage(0, 0);

    for (int it = 0; it < nIter; it++) {
        if (it + 1 < nIter) {
            load_stage((it + 1) << 5, (it + 1) & 1);
            asm volatile("cp.async.wait_group 1;\n");
        } else {
            asm volatile("cp.async.wait_group 0;\n");
        }
        __syncthreads();

        float* As = sm + (it & 1) * 5120;
        float* Ws = sm + (it & 1) * 5120 + 2560;
#pragma unroll
        for (int ks = 0; ks < 32; ks += 8) {
            wmma::fragment<wmma::matrix_a, 16, 16, 8, wmma::precision::tf32, wmma::row_major> a_frag[2];
            wmma::fragment<wmma::matrix_b, 16, 16, 8, wmma::precision::tf32, wmma::col_major> b_frag[2];
#pragma unroll
            for (int i = 0; i < 2; i++) {
                wmma::load_matrix_sync(a_frag[i], &As[(wr * 32 + i * 16) * LDS + ks], LDS);
#pragma unroll
                for (int t = 0; t < a_frag[i].num_elements; t++)
                    a_frag[i].x[t] = wmma::__float_to_tf32(a_frag[i].x[t]);
            }
#pragma unroll
            for (int j = 0; j < 2; j++) {
                wmma::load_matrix_sync(b_frag[j], &Ws[(wc * 32 + j * 16) * LDS + ks], LDS);
#pragma unroll
                for (int t = 0; t < b_frag[j].num_elements; t++)
                    b_frag[j].x[t] = wmma::__float_to_tf32(b_frag[j].x[t]);
            }
#pragma unroll
            for (int i = 0; i < 2; i++)
#pragma unroll
                for (int j = 0; j < 2; j++)
                    wmma::mma_sync(c_frag[i][j], a_frag[i], b_frag[j], c_frag[i][j]);
        }
        __syncthreads();
    }

    // Epilogue via shared staging (all cp.async groups drained by wait_group 0)
    float* Cs = sm;                 // [64][68]
    const int LDCS = 68;
#pragma unroll
    for (int i = 0; i < 2; i++)
#pragma unroll
        for (int j = 0; j < 2; j++)
            wmma::store_matrix_sync(&Cs[(wr * 32 + i * 16) * LDCS + wc * 32 + j * 16],
                                    c_frag[i][j], LDCS, wmma::mem_row_major);
    __syncthreads();
#pragma unroll
    for (int i = 0; i < 32; i++) {
        int idx = tid + i * 128;            // 0..4095
        int r = idx >> 6;
        int c = idx & 63;
        int m = m0 + r, n = n0 + c;
        float v = Cs[r * LDCS + c];
        if (bias)   v += bias[n];
        if (addend) v += addend[(size_t)m * ldadd + n];
        C[(size_t)m * ldc + n] = v;
    }
}

// ---------------------------------------------------------------------------
// fp32 SGEMM 64x64 (prologue only: embed split-K, state0)
// ---------------------------------------------------------------------------
__global__ __launch_bounds__(256)
void sgemm64(const float* __restrict__ A, int lda,
             const float* __restrict__ W, int ldw,
             const float* __restrict__ bias,
             const float* __restrict__ addend, int ldadd,
             float* __restrict__ C, int ldc,
             int M, int N, int K, int Kc)
{
    __shared__ float As[16][68];
    __shared__ float Ws[16][68];

    int tid = threadIdx.x;
    int tx = tid & 15, ty = tid >> 4;
    int m0 = blockIdx.y * 64, n0 = blockIdx.x * 64;

    int kstart = 0, kend = K;
    float* Cp = C;
    if (Kc > 0) {
        kstart = blockIdx.z * Kc;
        kend = min(K, kstart + Kc);
        Cp = C + (size_t)blockIdx.z * (size_t)M * (size_t)ldc;
    }

    float acc[4][4];
#pragma unroll
    for (int i = 0; i < 4; i++)
#pragma unroll
        for (int j = 0; j < 4; j++) acc[i][j] = 0.f;

    for (int k0 = kstart; k0 < kend; k0 += 16) {
#pragma unroll
        for (int i = 0; i < 4; i++) {
            int idx = tid + i * 256;
            int r = idx >> 4, kk = idx & 15;
            int gk = k0 + kk;
            int gm = m0 + r;
            As[kk][r] = (gm < M && gk < kend) ? A[(size_t)gm * lda + gk] : 0.f;
            int gn = n0 + r;
            Ws[kk][r] = (gn < N && gk < kend) ? W[(size_t)gn * ldw + gk] : 0.f;
        }
        __syncthreads();
#pragma unroll
        for (int kk = 0; kk < 16; kk++) {
            float4 a = *(const float4*)&As[kk][ty * 4];
            float4 b = *(const float4*)&Ws[kk][tx * 4];
            float av[4] = {a.x, a.y, a.z, a.w};
            float bv[4] = {b.x, b.y, b.z, b.w};
#pragma unroll
            for (int i = 0; i < 4; i++)
#pragma unroll
                for (int j = 0; j < 4; j++)
                    acc[i][j] = fmaf(av[i], bv[j], acc[i][j]);
        }
        __syncthreads();
    }

#pragma unroll
    for (int i = 0; i < 4; i++) {
        int m = m0 + ty * 4 + i;
        if (m >= M) continue;
#pragma unroll
        for (int j = 0; j < 4; j++) {
            int n = n0 + tx * 4 + j;
            if (n >= N) continue;
            float v = acc[i][j];
            if (bias)   v += bias[n];
            if (addend) v += addend[(size_t)m * ldadd + n];
            Cp[(size_t)m * ldc + n] = v;
        }
    }
}

// ---------------------------------------------------------------------------
// Small helper kernels
// ---------------------------------------------------------------------------
__global__ void wcat_fill(const float* __restrict__ sEmbed_w,
                          const float* __restrict__ sEmbed_b,
                          const float* __restrict__ w_hh,
                          const float* __restrict__ b_hh)
{
    int idx = blockIdx.x * blockDim.x + threadIdx.x;
    if (idx < 2048 * 512) {
        int n = idx >> 9;
        g_Wcat[idx] = (n < 512) ? sEmbed_w[idx] : w_hh[idx - 512 * 512];
    }
    if (idx < 2048)
        g_bcat[idx] = (idx < 512) ? sEmbed_b[idx] : b_hh[idx - 512];
}

__global__ void splitk_reduce(const float* __restrict__ bias)
{
    int idx = blockIdx.x * blockDim.x + threadIdx.x;   // 256*300
    if (idx >= 256 * 300) return;
    float s = 0.f;
#pragma unroll
    for (int z = 0; z < 16; z++) s += g_EbufPart[z * (256 * 300) + idx];
    g_emb[idx] = s + bias[idx % 300];
}

__global__ void yp_gather(const int* __restrict__ targets,
                          const float* __restrict__ tgt_emb)
{
    int idx = blockIdx.x * blockDim.x + threadIdx.x;   // 25*256*512
    if (idx >= TDEC * 256 * 512) return;
    int d = idx & 511;
    int row = idx >> 9;          // t*256 + b
    int b = row & 255;
    int t = row >> 8;
    int y = (t == 0) ? YDIM_ : targets[b * TDEC + (t - 1)];
    g_Yp[idx] = tgt_emb[(size_t)y * 512 + d];
}

// Fused attention: warp-per-t energy computation (2 block syncs total),
// then softmax over T=25 in one warp, then context accumulation.
__global__ __launch_bounds__(256)
void attn_kernel(const float* __restrict__ x,
                 const float* __restrict__ wEmbed_w,
                 const float* __restrict__ wEmbed_b)
{
    int b = blockIdx.x;
    int tid = threadIdx.x;
    int lane = tid & 31, warp = tid >> 5;
    __shared__ float sP[512];
    __shared__ float sW[512];
    __shared__ float alpha[32];

    sP[tid]       = g_C1[b * 2048 + tid];
    sP[tid + 256] = g_C1[b * 2048 + 256 + tid];
    sW[tid]       = wEmbed_w[tid];
    sW[tid + 256] = wEmbed_w[tid + 256];
    float wb = wEmbed_b[0];
    __syncthreads();

    // warp w handles t = w, w+8, w+16, w+24
    for (int t = warp; t < TENC; t += 8) {
        const float* xp = g_XP + (size_t)(b * TENC + t) * 512;
        float v = 0.f;
#pragma unroll
        for (int i = 0; i < 16; i++) {
            int d = lane + i * 32;
            v += sW[d] * tanhf(sP[d] + xp[d]);
        }
#pragma unroll
        for (int o = 16; o > 0; o >>= 1) v += __shfl_xor_sync(0xffffffffu, v, o);
        if (lane == 0) alpha[t] = v + wb;
    }
    __syncthreads();

    if (tid < 32) {
        float ev = (tid < TENC) ? alpha[tid] : -1e30f;
        float m = ev;
#pragma unroll
        for (int o = 16; o > 0; o >>= 1) m = fmaxf(m, __shfl_xor_sync(0xffffffffu, m, o));
        float ex = (tid < TENC) ? __expf(ev - m) : 0.f;
        float s = ex;
#pragma unroll
        for (int o = 16; o > 0; o >>= 1) s += __shfl_xor_sync(0xffffffffu, s, o);
        if (tid < TENC) alpha[tid] = ex / s;
    }
    __syncthreads();

    float c0 = 0.f, c1 = 0.f;
#pragma unroll
    for (int t = 0; t < TENC; t++) {
        const float* xr = x + (size_t)(b * TENC + t) * 512;
        float a = alpha[t];
        c0 = fmaf(a, xr[tid], c0);
        c1 = fmaf(a, xr[tid + 256], c1);
    }
    g_ctx[b * 512 + tid] = c0;
    g_ctx[b * 512 + 256 + tid] = c1;
}

// GRU gate fusion: reads g_GI (gi) and g_C1 (gh in cols 512..2047), updates state.
__global__ void gru_fuse(int t)
{
    int idx = blockIdx.x * blockDim.x + threadIdx.x;   // 256*512
    if (idx >= 256 * 512) return;
    int b = idx >> 9, j = idx & 511;
    const float* gi = g_GI + b * 1536;
    const float* gh = g_C1 + b * 2048 + 512;
    float ir = gi[j],        iz = gi[512 + j],  in_ = gi[1024 + j];
    float hr = gh[j],        hz = gh[512 + j],  hn  = gh[1024 + j];
    float r = 1.f / (1.f + __expf(-(ir + hr)));
    float z = 1.f / (1.f + __expf(-(iz + hz)));
    float n = tanhf(in_ + r * hn);
    const float* s_in  = g_states + (size_t)t * (256 * 512);
    float*       s_out = g_states + (size_t)(t + 1) * (256 * 512);
    s_out[idx] = (1.f - z) * n + z * s_in[idx];
}

// ---------------------------------------------------------------------------
// Launch
// ---------------------------------------------------------------------------
extern "C" void kernel_launch(void* const* d_in, const int* in_sizes, int n_in,
                              void* d_out, int out_size)
{
    int off = (n_in > 19) ? 1 : 0;
    const float* x          = (const float*)d_in[0];
    const int*   targets    = (const int*)  d_in[1];
    const float* eEmbed_w   = (const float*)d_in[2 + off];
    const float* eEmbed_b   = (const float*)d_in[3 + off];
    const float* embed_fc_w = (const float*)d_in[4 + off];
    const float* embed_fc_b = (const float*)d_in[5 + off];
    const float* sEmbed_w   = (const float*)d_in[6 + off];
    const float* sEmbed_b   = (const float*)d_in[7 + off];
    const float* xEmbed_w   = (const float*)d_in[8 + off];
    const float* xEmbed_b   = (const float*)d_in[9 + off];
    const float* wEmbed_w   = (const float*)d_in[10 + off];
    const float* wEmbed_b   = (const float*)d_in[11 + off];
    const float* tgt_emb    = (const float*)d_in[12 + off];
    const float* gru_w_ih   = (const float*)d_in[13 + off];
    const float* gru_w_hh   = (const float*)d_in[14 + off];
    const float* gru_b_ih   = (const float*)d_in[15 + off];
    const float* gru_b_hh   = (const float*)d_in[16 + off];
    const float* fc_w       = (const float*)d_in[17 + off];
    const float* fc_b       = (const float*)d_in[18 + off];
    float* out = (float*)d_out;

    float *pWcat, *pbcat, *pEbufPart, *pemb, *pXP, *pYp, *pGIY, *pstates, *pC1, *pGI, *pctx;
    cudaGetSymbolAddress((void**)&pWcat,     g_Wcat);
    cudaGetSymbolAddress((void**)&pbcat,     g_bcat);
    cudaGetSymbolAddress((void**)&pEbufPart, g_EbufPart);
    cudaGetSymbolAddress((void**)&pemb,      g_emb);
    cudaGetSymbolAddress((void**)&pXP,       g_XP);
    cudaGetSymbolAddress((void**)&pYp,       g_Yp);
    cudaGetSymbolAddress((void**)&pGIY,      g_GIY);
    cudaGetSymbolAddress((void**)&pstates,   g_states);
    cudaGetSymbolAddress((void**)&pC1,       g_C1);
    cudaGetSymbolAddress((void**)&pGI,       g_GI);
    cudaGetSymbolAddress((void**)&pctx,      g_ctx);

    // ---- Prologue (loop-invariant work) ----
    wcat_fill<<<4096, 256>>>(sEmbed_w, sEmbed_b, gru_w_hh, gru_b_hh);

    // embed = x_flat @ eEmbed_w.T  (K=12800, split-K 16-way, fp32)
    sgemm64<<<dim3(5, 4, 16), 256>>>(x, TENC * XDIM_, eEmbed_w, TENC * XDIM_,
                                     nullptr, nullptr, 0,
                                     pEbufPart, 300, 256, 300, TENC * XDIM_, 800);
    splitk_reduce<<<300, 256>>>(eEmbed_b);

    // state0 = emb @ embed_fc_w.T  (K=300, fp32)
    sgemm64<<<dim3(8, 4), 256>>>(pemb, 300, embed_fc_w, 300, embed_fc_b,
                                 nullptr, 0, pstates, 512, 256, 512, 300, 0);

    // xProj = x @ xEmbed_w.T  (TF32 pipelined, direct-store fast path)
    wgemm<<<dim3(4, 50), 256>>>(x, 512, xEmbed_w, 512, xEmbed_b,
                                pXP, 512, 6400, 512, 512, 0);

    // yProj gather, then GIY = Yp @ w_ih[:, :512].T + b_ih (TF32 pipelined)
    yp_gather<<<12800, 256>>>(targets, tgt_emb);
    wgemm<<<dim3(12, 50), 256>>>(pYp, 512, gru_w_ih, 1024, gru_b_ih,
                                 pGIY, 1536, 6400, 1536, 512, 0);

    // ---- Sequential decode loop (TF32 tensor cores, pipelined small GEMMs) ----
    for (int t = 0; t < TDEC; t++) {
        const float* state_in = pstates + (size_t)t * (256 * 512);

        // [sProj | gh] = state @ [sEmbed_w ; w_hh].T   (256 x 2048 x 512)
        wgemm_small<<<dim3(32, 4), 128>>>(state_in, 512, pWcat, 512, pbcat,
                                          nullptr, 0, pC1, 2048, 512);

        // attention -> context
        attn_kernel<<<256, 256>>>(x, wEmbed_w, wEmbed_b);

        // gi = GIY[t] + context @ w_ih[:, 512:1024].T  (256 x 1536 x 512)
        wgemm_small<<<dim3(24, 4), 128>>>(pctx, 512, gru_w_ih + 512, 1024, nullptr,
                                          pGIY + (size_t)t * (256 * 1536), 1536,
                                          pGI, 1536, 512);

        // GRU gates -> states[t+1]
        gru_fuse<<<512, 256>>>(t);
    }

    // ---- Epilogue: batched fc over all 25 states (TF32 pipelined, staged) ----
    wgemm<<<dim3(52, 50), 256>>>(pstates + 256 * 512, 512, fc_w, 512, fc_b,
                                 out, 0, 6400, YDIM_, 512, 1);
}

// round 13
// speedup vs baseline: 2.1854x; 1.0272x over previous
#include <cstdint>
#include <cuda_runtime.h>
#include <cuda_bf16.h>
#include <mma.h>

using namespace nvcuda;

// Problem constants
#define BB      256
#define TENC    25
#define XDIM_   512
#define SDIM_   512
#define ADIM_   512
#define YDIM_   6625
#define TDEC    25
#define EMBIN   300

// ---------------------------------------------------------------------------
// Static device scratch
// ---------------------------------------------------------------------------
__device__ __align__(256) float g_Wcat[2048 * 512];      // [sEmbed_w ; gru_w_hh]
__device__ __align__(256) float g_bcat[2048];
__device__ __align__(256) float g_EbufPart[16 * 256 * 300];
__device__ __align__(256) float g_emb[256 * 300];
__device__ __align__(256) float g_XP[6400 * 512];        // xProj, row = b*25+t
__device__ __align__(256) float g_Yp[6400 * 512];        // yProj, row = t*256+b
__device__ __align__(256) float g_GIY[6400 * 1536];      // precomputed gi (yProj part + b_ih)
__device__ __align__(256) float g_states[26 * 256 * 512];// state0 .. state25
__device__ __align__(256) float g_C1[256 * 2048];        // [sProj | gh] per step
__device__ __align__(256) float g_GI[256 * 1536];        // gi per step
__device__ __align__(256) float g_ctx[256 * 512];        // attention context

// ---------------------------------------------------------------------------
// cp.async helpers
// ---------------------------------------------------------------------------
__device__ __forceinline__ void cp_async16(void* smem_dst, const void* gptr, bool pred)
{
    unsigned int sa = (unsigned int)__cvta_generic_to_shared(smem_dst);
    int bytes = pred ? 16 : 0;
    asm volatile("cp.async.ca.shared.global [%0], [%1], 16, %2;\n"
                 :: "r"(sa), "l"(gptr), "r"(bytes));
}

// ---------------------------------------------------------------------------
// Wide-warp pipelined TF32 wmma GEMM (NT): C = A @ W^T + bias.
// Block 128x128, 4 warps (2x2), warp tile 64x64 (16 acc frags), BK=16,
// 2-stage cp.async double buffering, 128 threads.
// Per k8-chunk: 4 warps x 8 frag loads (~128 LDS cyc) for 64 HMMA (~256
// tensor cyc) => tensor-bound (prev 64x32 tiling was LDS/issue-bound).
// Bias folded into accumulator init. Direct fragment stores for the
// non-permuted interior path; permuted fc scatter (odd stride) uses the
// alignment-safe staged scalar path.
// Requires M % 128 == 0, K % 16 == 0.
// ---------------------------------------------------------------------------
__global__ __launch_bounds__(128)
void wgemmw(const float* __restrict__ A, int lda,
            const float* __restrict__ W, int ldw,
            const float* __restrict__ bias,
            float* __restrict__ C, int ldc,
            int M, int N, int K, int permuted)
{
    __shared__ float sm[10240];     // 40 KB: stage s at s*5120 (A 128x20, W 128x20)
    const int LDS = 20;

    int tid  = threadIdx.x;
    int warp = tid >> 5;
    int wr   = warp >> 1;           // 0..1 (64-row half)
    int wc   = warp & 1;            // 0..1 (64-col half)
    int m0 = blockIdx.y * 128;
    int n0 = blockIdx.x * 128;

    // ---- bias -> accumulator init (broadcast tile in smem) ----
    {
        float* Bs = sm;             // [16][136]
        const int LDB = 136;
        for (int i = tid; i < 16 * 128; i += 128) {
            int r = i >> 7, c = i & 127;
            int n = n0 + c;
            Bs[r * LDB + c] = (bias && n < N) ? bias[n] : 0.f;
        }
        __syncthreads();
    }
    wmma::fragment<wmma::accumulator, 16, 16, 8, float> c_frag[4][4];
    {
        float* Bs = sm;
        const int LDB = 136;
#pragma unroll
        for (int j = 0; j < 4; j++) {
            wmma::load_matrix_sync(c_frag[0][j], &Bs[wc * 64 + j * 16], LDB, wmma::mem_row_major);
#pragma unroll
            for (int i = 1; i < 4; i++)
#pragma unroll
                for (int t = 0; t < c_frag[0][j].num_elements; t++)
                    c_frag[i][j].x[t] = c_frag[0][j].x[t];
        }
        __syncthreads();
    }

    int nIter = K >> 4;

    // stage loader: A(128x16) + W(128x16), 512 float4 each, 128 threads
    auto load_stage = [&](int k0, int s) {
        float* As = sm + s * 5120;
        float* Ws = sm + s * 5120 + 2560;
#pragma unroll
        for (int i = 0; i < 4; i++) {
            int idx = tid + i * 128;        // 0..511
            int r  = idx >> 2;              // 0..127
            int c4 = (idx & 3) * 4;         // 0,4,8,12
            cp_async16(&As[r * LDS + c4], &A[(size_t)(m0 + r) * lda + k0 + c4], true);
            int gn = n0 + r;
            cp_async16(&Ws[r * LDS + c4], &W[(size_t)gn * ldw + k0 + c4], gn < N);
        }
        asm volatile("cp.async.commit_group;\n");
    };

    load_stage(0, 0);

    for (int it = 0; it < nIter; it++) {
        if (it + 1 < nIter) {
            load_stage((it + 1) << 4, (it + 1) & 1);
            asm volatile("cp.async.wait_group 1;\n");
        } else {
            asm volatile("cp.async.wait_group 0;\n");
        }
        __syncthreads();

        float* As = sm + (it & 1) * 5120;
        float* Ws = sm + (it & 1) * 5120 + 2560;
#pragma unroll
        for (int ks = 0; ks < 16; ks += 8) {
            wmma::fragment<wmma::matrix_a, 16, 16, 8, wmma::precision::tf32, wmma::row_major> a_frag[4];
            wmma::fragment<wmma::matrix_b, 16, 16, 8, wmma::precision::tf32, wmma::col_major> b_frag[4];
#pragma unroll
            for (int i = 0; i < 4; i++) {
                wmma::load_matrix_sync(a_frag[i], &As[(wr * 64 + i * 16) * LDS + ks], LDS);
#pragma unroll
                for (int t = 0; t < a_frag[i].num_elements; t++)
                    a_frag[i].x[t] = wmma::__float_to_tf32(a_frag[i].x[t]);
            }
#pragma unroll
            for (int j = 0; j < 4; j++) {
                wmma::load_matrix_sync(b_frag[j], &Ws[(wc * 64 + j * 16) * LDS + ks], LDS);
#pragma unroll
                for (int t = 0; t < b_frag[j].num_elements; t++)
                    b_frag[j].x[t] = wmma::__float_to_tf32(b_frag[j].x[t]);
            }
#pragma unroll
            for (int i = 0; i < 4; i++)
#pragma unroll
                for (int j = 0; j < 4; j++)
                    wmma::mma_sync(c_frag[i][j], a_frag[i], b_frag[j], c_frag[i][j]);
        }
        __syncthreads();
    }

    if (!permuted && n0 + 128 <= N) {
        // Fast path: direct fragment stores (even ldc => 8B-aligned v2 stores).
#pragma unroll
        for (int i = 0; i < 4; i++) {
            int m = m0 + wr * 64 + i * 16;
#pragma unroll
            for (int j = 0; j < 4; j++) {
                int n = n0 + wc * 64 + j * 16;
                wmma::store_matrix_sync(&C[(size_t)m * ldc + n],
                                        c_frag[i][j], ldc, wmma::mem_row_major);
            }
        }
    } else {
        // Staged path: 64-row halves through shared, guarded scalar writes.
        float* Cs = sm;             // [64][132] = 33.8 KB (fits in 40 KB)
        const int LDCS = 132;
#pragma unroll
        for (int p = 0; p < 2; p++) {
            if (wr == p) {
#pragma unroll
                for (int i = 0; i < 4; i++)
#pragma unroll
                    for (int j = 0; j < 4; j++)
                        wmma::store_matrix_sync(&Cs[(i * 16) * LDCS + wc * 64 + j * 16],
                                                c_frag[i][j], LDCS, wmma::mem_row_major);
            }
            __syncthreads();
#pragma unroll
            for (int i = 0; i < 64; i++) {
                int idx = tid + i * 128;    // 0..8191
                int r = idx >> 7;
                int c = idx & 127;
                int m = m0 + p * 64 + r;
                int n = n0 + c;
                if (n < N) {
                    float v = Cs[r * LDCS + c];
                    if (permuted) {
                        int b = m & 255;
                        int t = m >> 8;
                        C[(size_t)b * (TDEC * YDIM_) + (size_t)t * YDIM_ + n] = v;
                    } else {
                        C[(size_t)m * ldc + n] = v;
                    }
                }
            }
            __syncthreads();
        }
    }
}

// ---------------------------------------------------------------------------
// Small TF32 wmma GEMM (NT) for the decode loop: block 64x64, 4 warps (2x2),
// warp tile 32x32, BK=32 with 2-stage cp.async double buffering.
// C = A @ W^T (+bias[n]) (+addend[m][n]).
// ---------------------------------------------------------------------------
__global__ __launch_bounds__(128)
void wgemm_small(const float* __restrict__ A, int lda,
                 const float* __restrict__ W, int ldw,
                 const float* __restrict__ bias,
                 const float* __restrict__ addend, int ldadd,
                 float* __restrict__ C, int ldc, int K)
{
    __shared__ float sm[10240];     // 40 KB: stage s at s*5120 (A), +2560 (W)
    const int LDS = 40;             // 160B rows -> 16B-aligned cp.async dsts

    int tid  = threadIdx.x;
    int warp = tid >> 5;
    int wr   = warp >> 1;           // 0..1
    int wc   = warp & 1;            // 0..1
    int m0 = blockIdx.y * 64;
    int n0 = blockIdx.x * 64;

    wmma::fragment<wmma::accumulator, 16, 16, 8, float> c_frag[2][2];
#pragma unroll
    for (int i = 0; i < 2; i++)
#pragma unroll
        for (int j = 0; j < 2; j++)
            wmma::fill_fragment(c_frag[i][j], 0.0f);

    int nIter = K >> 5;

    auto load_stage = [&](int k0, int s) {
        float* As = sm + s * 5120;
        float* Ws = sm + s * 5120 + 2560;
#pragma unroll
        for (int i = 0; i < 4; i++) {
            int idx = tid + i * 128;        // 0..511
            int r  = idx >> 3;              // 0..63
            int c4 = (idx & 7) * 4;         // 0..28
            cp_async16(&As[r * LDS + c4], &A[(size_t)(m0 + r) * lda + k0 + c4], true);
            cp_async16(&Ws[r * LDS + c4], &W[(size_t)(n0 + r) * ldw + k0 + c4], true);
        }
        asm volatile("cp.async.commit_group;\n");
    };

    load_stage(0, 0);

    for (int it = 0; it < nIter; it++) {
        if (it + 1 < nIter) {
            load_stage((it + 1) << 5, (it + 1) & 1);
            asm volatile("cp.async.wait_group 1;\n");
        } else {
            asm volatile("cp.async.wait_group 0;\n");
        }
        __syncthreads();

        float* As = sm + (it & 1) * 5120;
        float* Ws = sm + (it & 1) * 5120 + 2560;
#pragma unroll
        for (int ks = 0; ks < 32; ks += 8) {
            wmma::fragment<wmma::matrix_a, 16, 16, 8, wmma::precision::tf32, wmma::row_major> a_frag[2];
            wmma::fragment<wmma::matrix_b, 16, 16, 8, wmma::precision::tf32, wmma::col_major> b_frag[2];
#pragma unroll
            for (int i = 0; i < 2; i++) {
                wmma::load_matrix_sync(a_frag[i], &As[(wr * 32 + i * 16) * LDS + ks], LDS);
#pragma unroll
                for (int t = 0; t < a_frag[i].num_elements; t++)
                    a_frag[i].x[t] = wmma::__float_to_tf32(a_frag[i].x[t]);
            }
#pragma unroll
            for (int j = 0; j < 2; j++) {
                wmma::load_matrix_sync(b_frag[j], &Ws[(wc * 32 + j * 16) * LDS + ks], LDS);
#pragma unroll
                for (int t = 0; t < b_frag[j].num_elements; t++)
                    b_frag[j].x[t] = wmma::__float_to_tf32(b_frag[j].x[t]);
            }
#pragma unroll
            for (int i = 0; i < 2; i++)
#pragma unroll
                for (int j = 0; j < 2; j++)
                    wmma::mma_sync(c_frag[i][j], a_frag[i], b_frag[j], c_frag[i][j]);
        }
        __syncthreads();
    }

    // Epilogue via shared staging
    float* Cs = sm;                 // [64][68]
    const int LDCS = 68;
#pragma unroll
    for (int i = 0; i < 2; i++)
#pragma unroll
        for (int j = 0; j < 2; j++)
            wmma::store_matrix_sync(&Cs[(wr * 32 + i * 16) * LDCS + wc * 32 + j * 16],
                                    c_frag[i][j], LDCS, wmma::mem_row_major);
    __syncthreads();
#pragma unroll
    for (int i = 0; i < 32; i++) {
        int idx = tid + i * 128;            // 0..4095
        int r = idx >> 6;
        int c = idx & 63;
        int m = m0 + r, n = n0 + c;
        float v = Cs[r * LDCS + c];
        if (bias)   v += bias[n];
        if (addend) v += addend[(size_t)m * ldadd + n];
        C[(size_t)m * ldc + n] = v;
    }
}

// ---------------------------------------------------------------------------
// fp32 SGEMM 64x64 (prologue only: embed split-K, state0)
// ---------------------------------------------------------------------------
__global__ __launch_bounds__(256)
void sgemm64(const float* __restrict__ A, int lda,
             const float* __restrict__ W, int ldw,
             const float* __restrict__ bias,
             const float* __restrict__ addend, int ldadd,
             float* __restrict__ C, int ldc,
             int M, int N, int K, int Kc)
{
    __shared__ float As[16][68];
    __shared__ float Ws[16][68];

    int tid = threadIdx.x;
    int tx = tid & 15, ty = tid >> 4;
    int m0 = blockIdx.y * 64, n0 = blockIdx.x * 64;

    int kstart = 0, kend = K;
    float* Cp = C;
    if (Kc > 0) {
        kstart = blockIdx.z * Kc;
        kend = min(K, kstart + Kc);
        Cp = C + (size_t)blockIdx.z * (size_t)M * (size_t)ldc;
    }

    float acc[4][4];
#pragma unroll
    for (int i = 0; i < 4; i++)
#pragma unroll
        for (int j = 0; j < 4; j++) acc[i][j] = 0.f;

    for (int k0 = kstart; k0 < kend; k0 += 16) {
#pragma unroll
        for (int i = 0; i < 4; i++) {
            int idx = tid + i * 256;
            int r = idx >> 4, kk = idx & 15;
            int gk = k0 + kk;
            int gm = m0 + r;
            As[kk][r] = (gm < M && gk < kend) ? A[(size_t)gm * lda + gk] : 0.f;
            int gn = n0 + r;
            Ws[kk][r] = (gn < N && gk < kend) ? W[(size_t)gn * ldw + gk] : 0.f;
        }
        __syncthreads();
#pragma unroll
        for (int kk = 0; kk < 16; kk++) {
            float4 a = *(const float4*)&As[kk][ty * 4];
            float4 b = *(const float4*)&Ws[kk][tx * 4];
            float av[4] = {a.x, a.y, a.z, a.w};
            float bv[4] = {b.x, b.y, b.z, b.w};
#pragma unroll
            for (int i = 0; i < 4; i++)
#pragma unroll
                for (int j = 0; j < 4; j++)
                    acc[i][j] = fmaf(av[i], bv[j], acc[i][j]);
        }
        __syncthreads();
    }

#pragma unroll
    for (int i = 0; i < 4; i++) {
        int m = m0 + ty * 4 + i;
        if (m >= M) continue;
#pragma unroll
        for (int j = 0; j < 4; j++) {
            int n = n0 + tx * 4 + j;
            if (n >= N) continue;
            float v = acc[i][j];
            if (bias)   v += bias[n];
            if (addend) v += addend[(size_t)m * ldadd + n];
            Cp[(size_t)m * ldc + n] = v;
        }
    }
}

// ---------------------------------------------------------------------------
// Small helper kernels
// ---------------------------------------------------------------------------
__global__ void wcat_fill(const float* __restrict__ sEmbed_w,
                          const float* __restrict__ sEmbed_b,
                          const float* __restrict__ w_hh,
                          const float* __restrict__ b_hh)
{
    int idx = blockIdx.x * blockDim.x + threadIdx.x;
    if (idx < 2048 * 512) {
        int n = idx >> 9;
        g_Wcat[idx] = (n < 512) ? sEmbed_w[idx] : w_hh[idx - 512 * 512];
    }
    if (idx < 2048)
        g_bcat[idx] = (idx < 512) ? sEmbed_b[idx] : b_hh[idx - 512];
}

__global__ void splitk_reduce(const float* __restrict__ bias)
{
    int idx = blockIdx.x * blockDim.x + threadIdx.x;   // 256*300
    if (idx >= 256 * 300) return;
    float s = 0.f;
#pragma unroll
    for (int z = 0; z < 16; z++) s += g_EbufPart[z * (256 * 300) + idx];
    g_emb[idx] = s + bias[idx % 300];
}

__global__ void yp_gather(const int* __restrict__ targets,
                          const float* __restrict__ tgt_emb)
{
    int idx = blockIdx.x * blockDim.x + threadIdx.x;   // 25*256*512
    if (idx >= TDEC * 256 * 512) return;
    int d = idx & 511;
    int row = idx >> 9;          // t*256 + b
    int b = row & 255;
    int t = row >> 8;
    int y = (t == 0) ? YDIM_ : targets[b * TDEC + (t - 1)];
    g_Yp[idx] = tgt_emb[(size_t)y * 512 + d];
}

// Fused attention: warp-per-t energy computation (2 block syncs total),
// then softmax over T=25 in one warp, then context accumulation.
__global__ __launch_bounds__(256)
void attn_kernel(const float* __restrict__ x,
                 const float* __restrict__ wEmbed_w,
                 const float* __restrict__ wEmbed_b)
{
    int b = blockIdx.x;
    int tid = threadIdx.x;
    int lane = tid & 31, warp = tid >> 5;
    __shared__ float sP[512];
    __shared__ float sW[512];
    __shared__ float alpha[32];

    sP[tid]       = g_C1[b * 2048 + tid];
    sP[tid + 256] = g_C1[b * 2048 + 256 + tid];
    sW[tid]       = wEmbed_w[tid];
    sW[tid + 256] = wEmbed_w[tid + 256];
    float wb = wEmbed_b[0];
    __syncthreads();

    // warp w handles t = w, w+8, w+16, w+24
    for (int t = warp; t < TENC; t += 8) {
        const float* xp = g_XP + (size_t)(b * TENC + t) * 512;
        float v = 0.f;
#pragma unroll
        for (int i = 0; i < 16; i++) {
            int d = lane + i * 32;
            v += sW[d] * tanhf(sP[d] + xp[d]);
        }
#pragma unroll
        for (int o = 16; o > 0; o >>= 1) v += __shfl_xor_sync(0xffffffffu, v, o);
        if (lane == 0) alpha[t] = v + wb;
    }
    __syncthreads();

    if (tid < 32) {
        float ev = (tid < TENC) ? alpha[tid] : -1e30f;
        float m = ev;
#pragma unroll
        for (int o = 16; o > 0; o >>= 1) m = fmaxf(m, __shfl_xor_sync(0xffffffffu, m, o));
        float ex = (tid < TENC) ? __expf(ev - m) : 0.f;
        float s = ex;
#pragma unroll
        for (int o = 16; o > 0; o >>= 1) s += __shfl_xor_sync(0xffffffffu, s, o);
        if (tid < TENC) alpha[tid] = ex / s;
    }
    __syncthreads();

    float c0 = 0.f, c1 = 0.f;
#pragma unroll
    for (int t = 0; t < TENC; t++) {
        const float* xr = x + (size_t)(b * TENC + t) * 512;
        float a = alpha[t];
        c0 = fmaf(a, xr[tid], c0);
        c1 = fmaf(a, xr[tid + 256], c1);
    }
    g_ctx[b * 512 + tid] = c0;
    g_ctx[b * 512 + 256 + tid] = c1;
}

// GRU gate fusion: reads g_GI (gi) and g_C1 (gh in cols 512..2047), updates state.
__global__ void gru_fuse(int t)
{
    int idx = blockIdx.x * blockDim.x + threadIdx.x;   // 256*512
    if (idx >= 256 * 512) return;
    int b = idx >> 9, j = idx & 511;
    const float* gi = g_GI + b * 1536;
    const float* gh = g_C1 + b * 2048 + 512;
    float ir = gi[j],        iz = gi[512 + j],  in_ = gi[1024 + j];
    float hr = gh[j],        hz = gh[512 + j],  hn  = gh[1024 + j];
    float r = 1.f / (1.f + __expf(-(ir + hr)));
    float z = 1.f / (1.f + __expf(-(iz + hz)));
    float n = tanhf(in_ + r * hn);
    const float* s_in  = g_states + (size_t)t * (256 * 512);
    float*       s_out = g_states + (size_t)(t + 1) * (256 * 512);
    s_out[idx] = (1.f - z) * n + z * s_in[idx];
}

// ---------------------------------------------------------------------------
// Launch
// ---------------------------------------------------------------------------
extern "C" void kernel_launch(void* const* d_in, const int* in_sizes, int n_in,
                              void* d_out, int out_size)
{
    int off = (n_in > 19) ? 1 : 0;
    const float* x          = (const float*)d_in[0];
    const int*   targets    = (const int*)  d_in[1];
    const float* eEmbed_w   = (const float*)d_in[2 + off];
    const float* eEmbed_b   = (const float*)d_in[3 + off];
    const float* embed_fc_w = (const float*)d_in[4 + off];
    const float* embed_fc_b = (const float*)d_in[5 + off];
    const float* sEmbed_w   = (const float*)d_in[6 + off];
    const float* sEmbed_b   = (const float*)d_in[7 + off];
    const float* xEmbed_w   = (const float*)d_in[8 + off];
    const float* xEmbed_b   = (const float*)d_in[9 + off];
    const float* wEmbed_w   = (const float*)d_in[10 + off];
    const float* wEmbed_b   = (const float*)d_in[11 + off];
    const float* tgt_emb    = (const float*)d_in[12 + off];
    const float* gru_w_ih   = (const float*)d_in[13 + off];
    const float* gru_w_hh   = (const float*)d_in[14 + off];
    const float* gru_b_ih   = (const float*)d_in[15 + off];
    const float* gru_b_hh   = (const float*)d_in[16 + off];
    const float* fc_w       = (const float*)d_in[17 + off];
    const float* fc_b       = (const float*)d_in[18 + off];
    float* out = (float*)d_out;

    float *pWcat, *pbcat, *pEbufPart, *pemb, *pXP, *pYp, *pGIY, *pstates, *pC1, *pGI, *pctx;
    cudaGetSymbolAddress((void**)&pWcat,     g_Wcat);
    cudaGetSymbolAddress((void**)&pbcat,     g_bcat);
    cudaGetSymbolAddress((void**)&pEbufPart, g_EbufPart);
    cudaGetSymbolAddress((void**)&pemb,      g_emb);
    cudaGetSymbolAddress((void**)&pXP,       g_XP);
    cudaGetSymbolAddress((void**)&pYp,       g_Yp);
    cudaGetSymbolAddress((void**)&pGIY,      g_GIY);
    cudaGetSymbolAddress((void**)&pstates,   g_states);
    cudaGetSymbolAddress((void**)&pC1,       g_C1);
    cudaGetSymbolAddress((void**)&pGI,       g_GI);
    cudaGetSymbolAddress((void**)&pctx,      g_ctx);

    // ---- Prologue (loop-invariant work) ----
    wcat_fill<<<4096, 256>>>(sEmbed_w, sEmbed_b, gru_w_hh, gru_b_hh);

    // embed = x_flat @ eEmbed_w.T  (K=12800, split-K 16-way, fp32)
    sgemm64<<<dim3(5, 4, 16), 256>>>(x, TENC * XDIM_, eEmbed_w, TENC * XDIM_,
                                     nullptr, nullptr, 0,
                                     pEbufPart, 300, 256, 300, TENC * XDIM_, 800);
    splitk_reduce<<<300, 256>>>(eEmbed_b);

    // state0 = emb @ embed_fc_w.T  (K=300, fp32)
    sgemm64<<<dim3(8, 4), 256>>>(pemb, 300, embed_fc_w, 300, embed_fc_b,
                                 nullptr, 0, pstates, 512, 256, 512, 300, 0);

    // xProj = x @ xEmbed_w.T  (wide-warp TF32, direct-store fast path)
    wgemmw<<<dim3(4, 50), 128>>>(x, 512, xEmbed_w, 512, xEmbed_b,
                                 pXP, 512, 6400, 512, 512, 0);

    // yProj gather, then GIY = Yp @ w_ih[:, :512].T + b_ih (wide-warp TF32)
    yp_gather<<<12800, 256>>>(targets, tgt_emb);
    wgemmw<<<dim3(12, 50), 128>>>(pYp, 512, gru_w_ih, 1024, gru_b_ih,
                                  pGIY, 1536, 6400, 1536, 512, 0);

    // ---- Sequential decode loop (TF32 tensor cores, pipelined small GEMMs) ----
    for (int t = 0; t < TDEC; t++) {
        const float* state_in = pstates + (size_t)t * (256 * 512);

        // [sProj | gh] = state @ [sEmbed_w ; w_hh].T   (256 x 2048 x 512)
        wgemm_small<<<dim3(32, 4), 128>>>(state_in, 512, pWcat, 512, pbcat,
                                          nullptr, 0, pC1, 2048, 512);

        // attention -> context
        attn_kernel<<<256, 256>>>(x, wEmbed_w, wEmbed_b);

        // gi = GIY[t] + context @ w_ih[:, 512:1024].T  (256 x 1536 x 512)
        wgemm_small<<<dim3(24, 4), 128>>>(pctx, 512, gru_w_ih + 512, 1024, nullptr,
                                          pGIY + (size_t)t * (256 * 1536), 1536,
                                          pGI, 1536, 512);

        // GRU gates -> states[t+1]
        gru_fuse<<<512, 256>>>(t);
    }

    // ---- Epilogue: batched fc over all 25 states (wide-warp TF32, staged) ----
    wgemmw<<<dim3(52, 50), 128>>>(pstates + 256 * 512, 512, fc_w, 512, fc_b,
                                  out, 0, 6400, YDIM_, 512, 1);
}

// round 15
// speedup vs baseline: 4.6894x; 2.1457x over previous
#include <cstdint>
#include <cuda_runtime.h>
#include <cuda_fp16.h>
#include <mma.h>

using namespace nvcuda;

// Problem constants
#define BB      256
#define TENC    25
#define XDIM_   512
#define SDIM_   512
#define ADIM_   512
#define YDIM_   6625
#define TDEC    25
#define EMBIN   300

// ---------------------------------------------------------------------------
// Static device scratch
// ---------------------------------------------------------------------------
__device__ __align__(256) float  g_bcat[2048];
__device__ __align__(256) float  g_EbufPart[16 * 256 * 300];
__device__ __align__(256) float  g_emb[256 * 300];
__device__ __align__(256) float  g_XP[6400 * 512];        // xProj (fp32)
__device__ __align__(256) float  g_GIY[6400 * 1536];      // gi (yProj part + b_ih)
__device__ __align__(256) float  g_states[26 * 256 * 512];// fp32 master states
__device__ __align__(256) float  g_C1[256 * 2048];        // [sProj | gh]
__device__ __align__(256) float  g_GI[256 * 1536];        // gi per step
// fp16 GEMM operands
__device__ __align__(256) __half g_hX[6400 * 512];
__device__ __align__(256) __half g_hXw[512 * 512];
__device__ __align__(256) __half g_hYp[6400 * 512];
__device__ __align__(256) __half g_hfcw[6625 * 512];
__device__ __align__(256) __half g_hWcat[2048 * 512];     // [sEmbed_w ; w_hh]
__device__ __align__(256) __half g_hWih1[1536 * 512];     // w_ih[:, 0:512]
__device__ __align__(256) __half g_hWih2[1536 * 512];     // w_ih[:, 512:1024]
__device__ __align__(256) __half g_hstates[26 * 256 * 512];
__device__ __align__(256) __half g_hctx[256 * 512];

// ---------------------------------------------------------------------------
// cp.async helper
// ---------------------------------------------------------------------------
__device__ __forceinline__ void cp_async16(void* smem_dst, const void* gptr, bool pred)
{
    unsigned int sa = (unsigned int)__cvta_generic_to_shared(smem_dst);
    int bytes = pred ? 16 : 0;
    asm volatile("cp.async.ca.shared.global [%0], [%1], 16, %2;\n"
                 :: "r"(sa), "l"(gptr), "r"(bytes));
}

// ---------------------------------------------------------------------------
// fp16 wmma GEMM (NT): C = A @ W^T + bias (fp32 out). Block 128x128,
// 4 warps (2x2), warp tile 64x64, BK=32 (2 k16 steps), 2-stage cp.async.
// Bias folded into accumulator init. Direct fragment stores for non-permuted
// interior; permuted fc scatter (odd stride) via staged scalar path.
// Requires M % 128 == 0, K % 32 == 0.
// ---------------------------------------------------------------------------
__global__ __launch_bounds__(128)
void hgemm128(const __half* __restrict__ A, int lda,
              const __half* __restrict__ W, int ldw,
              const float* __restrict__ bias,
              float* __restrict__ C, int ldc,
              int M, int N, int K, int permuted)
{
    __shared__ __align__(16) __half sm[20480];   // 40 KB; stage s at s*10240
    const int LDSH = 40;                          // 80B rows (16B-aligned)

    int tid  = threadIdx.x;
    int warp = tid >> 5;
    int wr   = warp >> 1;
    int wc   = warp & 1;
    int m0 = blockIdx.y * 128;
    int n0 = blockIdx.x * 128;

    // bias -> accumulator init via float view of smem
    {
        float* Bs = (float*)sm;      // [16][136]
        const int LDB = 136;
        for (int i = tid; i < 16 * 128; i += 128) {
            int r = i >> 7, c = i & 127;
            int n = n0 + c;
            Bs[r * LDB + c] = (bias && n < N) ? bias[n] : 0.f;
        }
        __syncthreads();
    }
    wmma::fragment<wmma::accumulator, 16, 16, 16, float> c_frag[4][4];
    {
        float* Bs = (float*)sm;
        const int LDB = 136;
#pragma unroll
        for (int j = 0; j < 4; j++) {
            wmma::load_matrix_sync(c_frag[0][j], &Bs[wc * 64 + j * 16], LDB, wmma::mem_row_major);
#pragma unroll
            for (int i = 1; i < 4; i++)
#pragma unroll
                for (int t = 0; t < c_frag[0][j].num_elements; t++)
                    c_frag[i][j].x[t] = c_frag[0][j].x[t];
        }
        __syncthreads();
    }

    int nIter = K >> 5;

    auto load_stage = [&](int k0, int s) {
        __half* As = sm + s * 10240;
        __half* Ws = As + 5120;
#pragma unroll
        for (int i = 0; i < 4; i++) {
            int idx = tid + i * 128;     // 0..511
            int r   = idx >> 2;          // 0..127
            int c16 = idx & 3;           // 8-half (16B) chunks
            cp_async16(&As[r * LDSH + c16 * 8], &A[(size_t)(m0 + r) * lda + k0 + c16 * 8], true);
            int gn = n0 + r;
            cp_async16(&Ws[r * LDSH + c16 * 8], &W[(size_t)gn * ldw + k0 + c16 * 8], gn < N);
        }
        asm volatile("cp.async.commit_group;\n");
    };

    load_stage(0, 0);

    for (int it = 0; it < nIter; it++) {
        if (it + 1 < nIter) {
            load_stage((it + 1) << 5, (it + 1) & 1);
            asm volatile("cp.async.wait_group 1;\n");
        } else {
            asm volatile("cp.async.wait_group 0;\n");
        }
        __syncthreads();

        __half* As = sm + (it & 1) * 10240;
        __half* Ws = As + 5120;
#pragma unroll
        for (int ks = 0; ks < 2; ks++) {
            wmma::fragment<wmma::matrix_a, 16, 16, 16, __half, wmma::row_major> a_frag[4];
            wmma::fragment<wmma::matrix_b, 16, 16, 16, __half, wmma::col_major> b_frag[4];
#pragma unroll
            for (int i = 0; i < 4; i++)
                wmma::load_matrix_sync(a_frag[i], &As[(wr * 64 + i * 16) * LDSH + ks * 16], LDSH);
#pragma unroll
            for (int j = 0; j < 4; j++)
                wmma::load_matrix_sync(b_frag[j], &Ws[(wc * 64 + j * 16) * LDSH + ks * 16], LDSH);
#pragma unroll
            for (int i = 0; i < 4; i++)
#pragma unroll
                for (int j = 0; j < 4; j++)
                    wmma::mma_sync(c_frag[i][j], a_frag[i], b_frag[j], c_frag[i][j]);
        }
        __syncthreads();
    }

    if (!permuted && n0 + 128 <= N) {
        // Direct fragment stores (even ldc => aligned vector stores)
#pragma unroll
        for (int i = 0; i < 4; i++) {
            int m = m0 + wr * 64 + i * 16;
#pragma unroll
            for (int j = 0; j < 4; j++) {
                int n = n0 + wc * 64 + j * 16;
                wmma::store_matrix_sync(&C[(size_t)m * ldc + n],
                                        c_frag[i][j], ldc, wmma::mem_row_major);
            }
        }
    } else {
        // Staged path: 64-row halves through shared (float view), scalar writes.
        float* Cs = (float*)sm;       // [64][132] = 33.8 KB (fits in 40 KB)
        const int LDCS = 132;
#pragma unroll
        for (int p = 0; p < 2; p++) {
            if (wr == p) {
#pragma unroll
                for (int i = 0; i < 4; i++)
#pragma unroll
                    for (int j = 0; j < 4; j++)
                        wmma::store_matrix_sync(&Cs[(i * 16) * LDCS + wc * 64 + j * 16],
                                                c_frag[i][j], LDCS, wmma::mem_row_major);
            }
            __syncthreads();
#pragma unroll
            for (int i = 0; i < 64; i++) {
                int idx = tid + i * 128;
                int r = idx >> 7;
                int c = idx & 127;
                int m = m0 + p * 64 + r;
                int n = n0 + c;
                if (n < N) {
                    float v = Cs[r * LDCS + c];
                    if (permuted) {
                        int b = m & 255;
                        int t = m >> 8;
                        C[(size_t)b * (TDEC * YDIM_) + (size_t)t * YDIM_ + n] = v;
                    } else {
                        C[(size_t)m * ldc + n] = v;
                    }
                }
            }
            __syncthreads();
        }
    }
}

// ---------------------------------------------------------------------------
// fp16 wmma GEMM (NT) for the decode loop: block 64x64, 4 warps (2x2),
// warp tile 32x32, BK=64 (4 k16 steps), 2-stage cp.async.
// C = A @ W^T (+bias[n]) (+addend[m][n]), fp32 out. K % 64 == 0.
// ---------------------------------------------------------------------------
__global__ __launch_bounds__(128)
void hgemm_small(const __half* __restrict__ A, int lda,
                 const __half* __restrict__ W, int ldw,
                 const float* __restrict__ bias,
                 const float* __restrict__ addend, int ldadd,
                 float* __restrict__ C, int ldc, int K)
{
    __shared__ __align__(16) __half sm[18432];   // 36 KB; stage s at s*9216
    const int LDSH = 72;                          // 144B rows (16B-aligned)

    int tid  = threadIdx.x;
    int warp = tid >> 5;
    int wr   = warp >> 1;
    int wc   = warp & 1;
    int m0 = blockIdx.y * 64;
    int n0 = blockIdx.x * 64;

    wmma::fragment<wmma::accumulator, 16, 16, 16, float> c_frag[2][2];
#pragma unroll
    for (int i = 0; i < 2; i++)
#pragma unroll
        for (int j = 0; j < 2; j++)
            wmma::fill_fragment(c_frag[i][j], 0.0f);

    int nIter = K >> 6;

    auto load_stage = [&](int k0, int s) {
        __half* As = sm + s * 9216;
        __half* Ws = As + 4608;
#pragma unroll
        for (int i = 0; i < 4; i++) {
            int idx = tid + i * 128;     // 0..511
            int r   = idx >> 3;          // 0..63
            int c16 = idx & 7;
            cp_async16(&As[r * LDSH + c16 * 8], &A[(size_t)(m0 + r) * lda + k0 + c16 * 8], true);
            cp_async16(&Ws[r * LDSH + c16 * 8], &W[(size_t)(n0 + r) * ldw + k0 + c16 * 8], true);
        }
        asm volatile("cp.async.commit_group;\n");
    };

    load_stage(0, 0);

    for (int it = 0; it < nIter; it++) {
        if (it + 1 < nIter) {
            load_stage((it + 1) << 6, (it + 1) & 1);
            asm volatile("cp.async.wait_group 1;\n");
        } else {
            asm volatile("cp.async.wait_group 0;\n");
        }
        __syncthreads();

        __half* As = sm + (it & 1) * 9216;
        __half* Ws = As + 4608;
#pragma unroll
        for (int ks = 0; ks < 4; ks++) {
            wmma::fragment<wmma::matrix_a, 16, 16, 16, __half, wmma::row_major> a_frag[2];
            wmma::fragment<wmma::matrix_b, 16, 16, 16, __half, wmma::col_major> b_frag[2];
#pragma unroll
            for (int i = 0; i < 2; i++)
                wmma::load_matrix_sync(a_frag[i], &As[(wr * 32 + i * 16) * LDSH + ks * 16], LDSH);
#pragma unroll
            for (int j = 0; j < 2; j++)
                wmma::load_matrix_sync(b_frag[j], &Ws[(wc * 32 + j * 16) * LDSH + ks * 16], LDSH);
#pragma unroll
            for (int i = 0; i < 2; i++)
#pragma unroll
                for (int j = 0; j < 2; j++)
                    wmma::mma_sync(c_frag[i][j], a_frag[i], b_frag[j], c_frag[i][j]);
        }
        __syncthreads();
    }

    // Epilogue via float staging
    float* Cs = (float*)sm;           // [64][68] = 17.4 KB
    const int LDCS = 68;
#pragma unroll
    for (int i = 0; i < 2; i++)
#pragma unroll
        for (int j = 0; j < 2; j++)
            wmma::store_matrix_sync(&Cs[(wr * 32 + i * 16) * LDCS + wc * 32 + j * 16],
                                    c_frag[i][j], LDCS, wmma::mem_row_major);
    __syncthreads();
#pragma unroll
    for (int i = 0; i < 32; i++) {
        int idx = tid + i * 128;
        int r = idx >> 6;
        int c = idx & 63;
        int m = m0 + r, n = n0 + c;
        float v = Cs[r * LDCS + c];
        if (bias)   v += bias[n];
        if (addend) v += addend[(size_t)m * ldadd + n];
        C[(size_t)m * ldc + n] = v;
    }
}

// ---------------------------------------------------------------------------
// fp32 SGEMM 64x64 (prologue only: embed split-K, state0)
// ---------------------------------------------------------------------------
__global__ __launch_bounds__(256)
void sgemm64(const float* __restrict__ A, int lda,
             const float* __restrict__ W, int ldw,
             const float* __restrict__ bias,
             const float* __restrict__ addend, int ldadd,
             float* __restrict__ C, int ldc,
             int M, int N, int K, int Kc)
{
    __shared__ float As[16][68];
    __shared__ float Ws[16][68];

    int tid = threadIdx.x;
    int tx = tid & 15, ty = tid >> 4;
    int m0 = blockIdx.y * 64, n0 = blockIdx.x * 64;

    int kstart = 0, kend = K;
    float* Cp = C;
    if (Kc > 0) {
        kstart = blockIdx.z * Kc;
        kend = min(K, kstart + Kc);
        Cp = C + (size_t)blockIdx.z * (size_t)M * (size_t)ldc;
    }

    float acc[4][4];
#pragma unroll
    for (int i = 0; i < 4; i++)
#pragma unroll
        for (int j = 0; j < 4; j++) acc[i][j] = 0.f;

    for (int k0 = kstart; k0 < kend; k0 += 16) {
#pragma unroll
        for (int i = 0; i < 4; i++) {
            int idx = tid + i * 256;
            int r = idx >> 4, kk = idx & 15;
            int gk = k0 + kk;
            int gm = m0 + r;
            As[kk][r] = (gm < M && gk < kend) ? A[(size_t)gm * lda + gk] : 0.f;
            int gn = n0 + r;
            Ws[kk][r] = (gn < N && gk < kend) ? W[(size_t)gn * ldw + gk] : 0.f;
        }
        __syncthreads();
#pragma unroll
        for (int kk = 0; kk < 16; kk++) {
            float4 a = *(const float4*)&As[kk][ty * 4];
            float4 b = *(const float4*)&Ws[kk][tx * 4];
            float av[4] = {a.x, a.y, a.z, a.w};
            float bv[4] = {b.x, b.y, b.z, b.w};
#pragma unroll
            for (int i = 0; i < 4; i++)
#pragma unroll
                for (int j = 0; j < 4; j++)
                    acc[i][j] = fmaf(av[i], bv[j], acc[i][j]);
        }
        __syncthreads();
    }

#pragma unroll
    for (int i = 0; i < 4; i++) {
        int m = m0 + ty * 4 + i;
        if (m >= M) continue;
#pragma unroll
        for (int j = 0; j < 4; j++) {
            int n = n0 + tx * 4 + j;
            if (n >= N) continue;
            float v = acc[i][j];
            if (bias)   v += bias[n];
            if (addend) v += addend[(size_t)m * ldadd + n];
            Cp[(size_t)m * ldc + n] = v;
        }
    }
}

// ---------------------------------------------------------------------------
// Conversion / helper kernels
// ---------------------------------------------------------------------------
__global__ void cvt_h(const float* __restrict__ src, __half* __restrict__ dst, int n)
{
    int i = blockIdx.x * blockDim.x + threadIdx.x;
    if (i < n) dst[i] = __float2half_rn(src[i]);
}

__global__ void cvt_wih(const float* __restrict__ w)   // [1536][1024]
{
    int idx = blockIdx.x * blockDim.x + threadIdx.x;   // 1536*512
    if (idx >= 1536 * 512) return;
    int n = idx >> 9, k = idx & 511;
    g_hWih1[idx] = __float2half_rn(w[n * 1024 + k]);
    g_hWih2[idx] = __float2half_rn(w[n * 1024 + 512 + k]);
}

__global__ void wcat_fill(const float* __restrict__ sEmbed_w,
                          const float* __restrict__ sEmbed_b,
                          const float* __restrict__ w_hh,
                          const float* __restrict__ b_hh)
{
    int idx = blockIdx.x * blockDim.x + threadIdx.x;
    if (idx < 2048 * 512) {
        int n = idx >> 9;
        float v = (n < 512) ? sEmbed_w[idx] : w_hh[idx - 512 * 512];
        g_hWcat[idx] = __float2half_rn(v);
    }
    if (idx < 2048)
        g_bcat[idx] = (idx < 512) ? sEmbed_b[idx] : b_hh[idx - 512];
}

__global__ void splitk_reduce(const float* __restrict__ bias)
{
    int idx = blockIdx.x * blockDim.x + threadIdx.x;   // 256*300
    if (idx >= 256 * 300) return;
    float s = 0.f;
#pragma unroll
    for (int z = 0; z < 16; z++) s += g_EbufPart[z * (256 * 300) + idx];
    g_emb[idx] = s + bias[idx % 300];
}

__global__ void yp_gather(const int* __restrict__ targets,
                          const float* __restrict__ tgt_emb)
{
    int idx = blockIdx.x * blockDim.x + threadIdx.x;   // 25*256*512
    if (idx >= TDEC * 256 * 512) return;
    int d = idx & 511;
    int row = idx >> 9;          // t*256 + b
    int b = row & 255;
    int t = row >> 8;
    int y = (t == 0) ? YDIM_ : targets[b * TDEC + (t - 1)];
    g_hYp[idx] = __float2half_rn(tgt_emb[(size_t)y * 512 + d]);
}

// Fused attention: warp-per-t energies, softmax, context (writes fp16 ctx).
__global__ __launch_bounds__(256)
void attn_kernel(const float* __restrict__ x,
                 const float* __restrict__ wEmbed_w,
                 const float* __restrict__ wEmbed_b)
{
    int b = blockIdx.x;
    int tid = threadIdx.x;
    int lane = tid & 31, warp = tid >> 5;
    __shared__ float sP[512];
    __shared__ float sW[512];
    __shared__ float alpha[32];

    sP[tid]       = g_C1[b * 2048 + tid];
    sP[tid + 256] = g_C1[b * 2048 + 256 + tid];
    sW[tid]       = wEmbed_w[tid];
    sW[tid + 256] = wEmbed_w[tid + 256];
    float wb = wEmbed_b[0];
    __syncthreads();

    for (int t = warp; t < TENC; t += 8) {
        const float* xp = g_XP + (size_t)(b * TENC + t) * 512;
        float v = 0.f;
#pragma unroll
        for (int i = 0; i < 16; i++) {
            int d = lane + i * 32;
            v += sW[d] * tanhf(sP[d] + xp[d]);
        }
#pragma unroll
        for (int o = 16; o > 0; o >>= 1) v += __shfl_xor_sync(0xffffffffu, v, o);
        if (lane == 0) alpha[t] = v + wb;
    }
    __syncthreads();

    if (tid < 32) {
        float ev = (tid < TENC) ? alpha[tid] : -1e30f;
        float m = ev;
#pragma unroll
        for (int o = 16; o > 0; o >>= 1) m = fmaxf(m, __shfl_xor_sync(0xffffffffu, m, o));
        float ex = (tid < TENC) ? __expf(ev - m) : 0.f;
        float s = ex;
#pragma unroll
        for (int o = 16; o > 0; o >>= 1) s += __shfl_xor_sync(0xffffffffu, s, o);
        if (tid < TENC) alpha[tid] = ex / s;
    }
    __syncthreads();

    float c0 = 0.f, c1 = 0.f;
#pragma unroll
    for (int t = 0; t < TENC; t++) {
        const float* xr = x + (size_t)(b * TENC + t) * 512;
        float a = alpha[t];
        c0 = fmaf(a, xr[tid], c0);
        c1 = fmaf(a, xr[tid + 256], c1);
    }
    g_hctx[b * 512 + tid]       = __float2half_rn(c0);
    g_hctx[b * 512 + 256 + tid] = __float2half_rn(c1);
}

// GRU gate fusion: fp32 recurrence + fp16 state copy for GEMM consumers.
__global__ void gru_fuse(int t)
{
    int idx = blockIdx.x * blockDim.x + threadIdx.x;   // 256*512
    if (idx >= 256 * 512) return;
    int b = idx >> 9, j = idx & 511;
    const float* gi = g_GI + b * 1536;
    const float* gh = g_C1 + b * 2048 + 512;
    float ir = gi[j],        iz = gi[512 + j],  in_ = gi[1024 + j];
    float hr = gh[j],        hz = gh[512 + j],  hn  = gh[1024 + j];
    float r = 1.f / (1.f + __expf(-(ir + hr)));
    float z = 1.f / (1.f + __expf(-(iz + hz)));
    float n = tanhf(in_ + r * hn);
    const float* s_in  = g_states + (size_t)t * (256 * 512);
    float v = (1.f - z) * n + z * s_in[idx];
    g_states[(size_t)(t + 1) * (256 * 512) + idx]  = v;
    g_hstates[(size_t)(t + 1) * (256 * 512) + idx] = __float2half_rn(v);
}

// ---------------------------------------------------------------------------
// Launch
// ---------------------------------------------------------------------------
extern "C" void kernel_launch(void* const* d_in, const int* in_sizes, int n_in,
                              void* d_out, int out_size)
{
    int off = (n_in > 19) ? 1 : 0;
    const float* x          = (const float*)d_in[0];
    const int*   targets    = (const int*)  d_in[1];
    const float* eEmbed_w   = (const float*)d_in[2 + off];
    const float* eEmbed_b   = (const float*)d_in[3 + off];
    const float* embed_fc_w = (const float*)d_in[4 + off];
    const float* embed_fc_b = (const float*)d_in[5 + off];
    const float* sEmbed_w   = (const float*)d_in[6 + off];
    const float* sEmbed_b   = (const float*)d_in[7 + off];
    const float* xEmbed_w   = (const float*)d_in[8 + off];
    const float* xEmbed_b   = (const float*)d_in[9 + off];
    const float* wEmbed_w   = (const float*)d_in[10 + off];
    const float* wEmbed_b   = (const float*)d_in[11 + off];
    const float* tgt_emb    = (const float*)d_in[12 + off];
    const float* gru_w_ih   = (const float*)d_in[13 + off];
    const float* gru_w_hh   = (const float*)d_in[14 + off];
    const float* gru_b_ih   = (const float*)d_in[15 + off];
    const float* gru_b_hh   = (const float*)d_in[16 + off];
    const float* fc_w       = (const float*)d_in[17 + off];
    const float* fc_b       = (const float*)d_in[18 + off];
    float* out = (float*)d_out;

    float *pbcat, *pEbufPart, *pemb, *pXP, *pGIY, *pstates, *pC1, *pGI;
    __half *phX, *phXw, *phYp, *phfcw, *phWcat, *phWih1, *phWih2, *phstates, *phctx;
    cudaGetSymbolAddress((void**)&pbcat,     g_bcat);
    cudaGetSymbolAddress((void**)&pEbufPart, g_EbufPart);
    cudaGetSymbolAddress((void**)&pemb,      g_emb);
    cudaGetSymbolAddress((void**)&pXP,       g_XP);
    cudaGetSymbolAddress((void**)&pGIY,      g_GIY);
    cudaGetSymbolAddress((void**)&pstates,   g_states);
    cudaGetSymbolAddress((void**)&pC1,       g_C1);
    cudaGetSymbolAddress((void**)&pGI,       g_GI);
    cudaGetSymbolAddress((void**)&phX,       g_hX);
    cudaGetSymbolAddress((void**)&phXw,      g_hXw);
    cudaGetSymbolAddress((void**)&phYp,      g_hYp);
    cudaGetSymbolAddress((void**)&phfcw,     g_hfcw);
    cudaGetSymbolAddress((void**)&phWcat,    g_hWcat);
    cudaGetSymbolAddress((void**)&phWih1,    g_hWih1);
    cudaGetSymbolAddress((void**)&phWih2,    g_hWih2);
    cudaGetSymbolAddress((void**)&phstates,  g_hstates);
    cudaGetSymbolAddress((void**)&phctx,     g_hctx);

    // ---- Prologue: conversions + loop-invariant work ----
    wcat_fill<<<4096, 256>>>(sEmbed_w, sEmbed_b, gru_w_hh, gru_b_hh);
    cvt_h<<<(6400 * 512 + 255) / 256, 256>>>(x, phX, 6400 * 512);
    cvt_h<<<(YDIM_ * 512 + 255) / 256, 256>>>(fc_w, phfcw, YDIM_ * 512);
    cvt_h<<<(512 * 512 + 255) / 256, 256>>>(xEmbed_w, phXw, 512 * 512);
    cvt_wih<<<(1536 * 512 + 255) / 256, 256>>>(gru_w_ih);

    // embed = x_flat @ eEmbed_w.T  (K=12800, split-K 16-way, fp32)
    sgemm64<<<dim3(5, 4, 16), 256>>>(x, TENC * XDIM_, eEmbed_w, TENC * XDIM_,
                                     nullptr, nullptr, 0,
                                     pEbufPart, 300, 256, 300, TENC * XDIM_, 800);
    splitk_reduce<<<300, 256>>>(eEmbed_b);

    // state0 = emb @ embed_fc_w.T  (K=300, fp32) -> also fp16 copy
    sgemm64<<<dim3(8, 4), 256>>>(pemb, 300, embed_fc_w, 300, embed_fc_b,
                                 nullptr, 0, pstates, 512, 256, 512, 300, 0);
    cvt_h<<<(256 * 512 + 255) / 256, 256>>>(pstates, phstates, 256 * 512);

    // xProj = x @ xEmbed_w.T  (fp16 wmma)
    hgemm128<<<dim3(4, 50), 128>>>(phX, 512, phXw, 512, xEmbed_b,
                                   pXP, 512, 6400, 512, 512, 0);

    // yProj gather (fp16), then GIY = Yp @ w_ih[:, :512].T + b_ih (fp16 wmma)
    yp_gather<<<12800, 256>>>(targets, tgt_emb);
    hgemm128<<<dim3(12, 50), 128>>>(phYp, 512, phWih1, 512, gru_b_ih,
                                    pGIY, 1536, 6400, 1536, 512, 0);

    // ---- Sequential decode loop (fp16 tensor cores) ----
    for (int t = 0; t < TDEC; t++) {
        const __half* hstate_in = phstates + (size_t)t * (256 * 512);

        // [sProj | gh] = state @ [sEmbed_w ; w_hh].T   (256 x 2048 x 512)
        hgemm_small<<<dim3(32, 4), 128>>>(hstate_in, 512, phWcat, 512, pbcat,
                                          nullptr, 0, pC1, 2048, 512);

        // attention -> context (fp16)
        attn_kernel<<<256, 256>>>(x, wEmbed_w, wEmbed_b);

        // gi = GIY[t] + context @ w_ih[:, 512:1024].T  (256 x 1536 x 512)
        hgemm_small<<<dim3(24, 4), 128>>>(phctx, 512, phWih2, 512, nullptr,
                                          pGIY + (size_t)t * (256 * 1536), 1536,
                                          pGI, 1536, 512);

        // GRU gates -> states[t+1] (fp32 + fp16 copy)
        gru_fuse<<<512, 256>>>(t);
    }

    // ---- Epilogue: batched fc over all 25 states (fp16 wmma, permuted) ----
    hgemm128<<<dim3(52, 50), 128>>>(phstates + 256 * 512, 512, phfcw, 512, fc_b,
                                    out, 0, 6400, YDIM_, 512, 1);
}

// round 16
// speedup vs baseline: 5.1187x; 1.0915x over previous
#include <cstdint>
#include <cuda_runtime.h>
#include <cuda_fp16.h>
#include <mma.h>

using namespace nvcuda;

// Problem constants
#define BB      256
#define TENC    25
#define XDIM_   512
#define SDIM_   512
#define ADIM_   512
#define YDIM_   6625
#define TDEC    25
#define EMBIN   300

// ---------------------------------------------------------------------------
// Static device scratch
// ---------------------------------------------------------------------------
__device__ __align__(256) float  g_bcat[2048];
__device__ __align__(256) float  g_EbufPart[16 * 256 * 300];
__device__ __align__(256) float  g_emb[256 * 300];
__device__ __align__(256) float  g_XP[6400 * 512];        // xProj (fp32)
__device__ __align__(256) float  g_GIY[6400 * 1536];      // gi (yProj part + b_ih)
__device__ __align__(256) float  g_XW2f[6400 * 1536];     // x @ w_ih[:,512:1024]^T (fp32)
__device__ __align__(256) float  g_states[26 * 256 * 512];// fp32 master states
__device__ __align__(256) float  g_C1[256 * 2048];        // [sProj | gh]
// fp16 GEMM operands
__device__ __align__(256) __half g_hX[6400 * 512];
__device__ __align__(256) __half g_hXw[512 * 512];
__device__ __align__(256) __half g_hYp[6400 * 512];
__device__ __align__(256) __half g_hfcw[6625 * 512];
__device__ __align__(256) __half g_hWcat[2048 * 512];     // [sEmbed_w ; w_hh]
__device__ __align__(256) __half g_hWih1[1536 * 512];     // w_ih[:, 0:512]
__device__ __align__(256) __half g_hWih2[1536 * 512];     // w_ih[:, 512:1024]
__device__ __align__(256) __half g_hXW2[6400 * 1536];     // fp16 copy of XW2
__device__ __align__(256) __half g_hstates[26 * 256 * 512];

// ---------------------------------------------------------------------------
// cp.async helper
// ---------------------------------------------------------------------------
__device__ __forceinline__ void cp_async16(void* smem_dst, const void* gptr, bool pred)
{
    unsigned int sa = (unsigned int)__cvta_generic_to_shared(smem_dst);
    int bytes = pred ? 16 : 0;
    asm volatile("cp.async.ca.shared.global [%0], [%1], 16, %2;\n"
                 :: "r"(sa), "l"(gptr), "r"(bytes));
}

// ---------------------------------------------------------------------------
// fp16 wmma GEMM (NT): C = A @ W^T + bias (fp32 out). Block 128x128,
// 4 warps (2x2), warp tile 64x64, BK=32, 2-stage cp.async.
// permuted=1: row m=(t*256+b) scattered to out[b][t][n] via staged path.
// ---------------------------------------------------------------------------
__global__ __launch_bounds__(128)
void hgemm128(const __half* __restrict__ A, int lda,
              const __half* __restrict__ W, int ldw,
              const float* __restrict__ bias,
              float* __restrict__ C, int ldc,
              int M, int N, int K, int permuted)
{
    __shared__ __align__(16) __half sm[20480];   // 40 KB; stage s at s*10240
    const int LDSH = 40;

    int tid  = threadIdx.x;
    int warp = tid >> 5;
    int wr   = warp >> 1;
    int wc   = warp & 1;
    int m0 = blockIdx.y * 128;
    int n0 = blockIdx.x * 128;

    {
        float* Bs = (float*)sm;      // [16][136]
        const int LDB = 136;
        for (int i = tid; i < 16 * 128; i += 128) {
            int r = i >> 7, c = i & 127;
            int n = n0 + c;
            Bs[r * LDB + c] = (bias && n < N) ? bias[n] : 0.f;
        }
        __syncthreads();
    }
    wmma::fragment<wmma::accumulator, 16, 16, 16, float> c_frag[4][4];
    {
        float* Bs = (float*)sm;
        const int LDB = 136;
#pragma unroll
        for (int j = 0; j < 4; j++) {
            wmma::load_matrix_sync(c_frag[0][j], &Bs[wc * 64 + j * 16], LDB, wmma::mem_row_major);
#pragma unroll
            for (int i = 1; i < 4; i++)
#pragma unroll
                for (int t = 0; t < c_frag[0][j].num_elements; t++)
                    c_frag[i][j].x[t] = c_frag[0][j].x[t];
        }
        __syncthreads();
    }

    int nIter = K >> 5;

    auto load_stage = [&](int k0, int s) {
        __half* As = sm + s * 10240;
        __half* Ws = As + 5120;
#pragma unroll
        for (int i = 0; i < 4; i++) {
            int idx = tid + i * 128;
            int r   = idx >> 2;
            int c16 = idx & 3;
            cp_async16(&As[r * LDSH + c16 * 8], &A[(size_t)(m0 + r) * lda + k0 + c16 * 8], true);
            int gn = n0 + r;
            cp_async16(&Ws[r * LDSH + c16 * 8], &W[(size_t)gn * ldw + k0 + c16 * 8], gn < N);
        }
        asm volatile("cp.async.commit_group;\n");
    };

    load_stage(0, 0);

    for (int it = 0; it < nIter; it++) {
        if (it + 1 < nIter) {
            load_stage((it + 1) << 5, (it + 1) & 1);
            asm volatile("cp.async.wait_group 1;\n");
        } else {
            asm volatile("cp.async.wait_group 0;\n");
        }
        __syncthreads();

        __half* As = sm + (it & 1) * 10240;
        __half* Ws = As + 5120;
#pragma unroll
        for (int ks = 0; ks < 2; ks++) {
            wmma::fragment<wmma::matrix_a, 16, 16, 16, __half, wmma::row_major> a_frag[4];
            wmma::fragment<wmma::matrix_b, 16, 16, 16, __half, wmma::col_major> b_frag[4];
#pragma unroll
            for (int i = 0; i < 4; i++)
                wmma::load_matrix_sync(a_frag[i], &As[(wr * 64 + i * 16) * LDSH + ks * 16], LDSH);
#pragma unroll
            for (int j = 0; j < 4; j++)
                wmma::load_matrix_sync(b_frag[j], &Ws[(wc * 64 + j * 16) * LDSH + ks * 16], LDSH);
#pragma unroll
            for (int i = 0; i < 4; i++)
#pragma unroll
                for (int j = 0; j < 4; j++)
                    wmma::mma_sync(c_frag[i][j], a_frag[i], b_frag[j], c_frag[i][j]);
        }
        __syncthreads();
    }

    if (!permuted && n0 + 128 <= N) {
#pragma unroll
        for (int i = 0; i < 4; i++) {
            int m = m0 + wr * 64 + i * 16;
#pragma unroll
            for (int j = 0; j < 4; j++) {
                int n = n0 + wc * 64 + j * 16;
                wmma::store_matrix_sync(&C[(size_t)m * ldc + n],
                                        c_frag[i][j], ldc, wmma::mem_row_major);
            }
        }
    } else {
        float* Cs = (float*)sm;
        const int LDCS = 132;
#pragma unroll
        for (int p = 0; p < 2; p++) {
            if (wr == p) {
#pragma unroll
                for (int i = 0; i < 4; i++)
#pragma unroll
                    for (int j = 0; j < 4; j++)
                        wmma::store_matrix_sync(&Cs[(i * 16) * LDCS + wc * 64 + j * 16],
                                                c_frag[i][j], LDCS, wmma::mem_row_major);
            }
            __syncthreads();
#pragma unroll
            for (int i = 0; i < 64; i++) {
                int idx = tid + i * 128;
                int r = idx >> 7;
                int c = idx & 127;
                int m = m0 + p * 64 + r;
                int n = n0 + c;
                if (n < N) {
                    float v = Cs[r * LDCS + c];
                    if (permuted) {
                        int b = m & 255;
                        int t = m >> 8;
                        C[(size_t)b * (TDEC * YDIM_) + (size_t)t * YDIM_ + n] = v;
                    } else {
                        C[(size_t)m * ldc + n] = v;
                    }
                }
            }
            __syncthreads();
        }
    }
}

// ---------------------------------------------------------------------------
// fp16 wmma GEMM (NT) small: block 64x64, 4 warps, warp tile 32x32, BK=64,
// 2-stage cp.async. C = A @ W^T (+bias[n]). K % 64 == 0.
// ---------------------------------------------------------------------------
__global__ __launch_bounds__(128)
void hgemm_small(const __half* __restrict__ A, int lda,
                 const __half* __restrict__ W, int ldw,
                 const float* __restrict__ bias,
                 float* __restrict__ C, int ldc, int K)
{
    __shared__ __align__(16) __half sm[18432];
    const int LDSH = 72;

    int tid  = threadIdx.x;
    int warp = tid >> 5;
    int wr   = warp >> 1;
    int wc   = warp & 1;
    int m0 = blockIdx.y * 64;
    int n0 = blockIdx.x * 64;

    wmma::fragment<wmma::accumulator, 16, 16, 16, float> c_frag[2][2];
#pragma unroll
    for (int i = 0; i < 2; i++)
#pragma unroll
        for (int j = 0; j < 2; j++)
            wmma::fill_fragment(c_frag[i][j], 0.0f);

    int nIter = K >> 6;

    auto load_stage = [&](int k0, int s) {
        __half* As = sm + s * 9216;
        __half* Ws = As + 4608;
#pragma unroll
        for (int i = 0; i < 4; i++) {
            int idx = tid + i * 128;
            int r   = idx >> 3;
            int c16 = idx & 7;
            cp_async16(&As[r * LDSH + c16 * 8], &A[(size_t)(m0 + r) * lda + k0 + c16 * 8], true);
            cp_async16(&Ws[r * LDSH + c16 * 8], &W[(size_t)(n0 + r) * ldw + k0 + c16 * 8], true);
        }
        asm volatile("cp.async.commit_group;\n");
    };

    load_stage(0, 0);

    for (int it = 0; it < nIter; it++) {
        if (it + 1 < nIter) {
            load_stage((it + 1) << 6, (it + 1) & 1);
            asm volatile("cp.async.wait_group 1;\n");
        } else {
            asm volatile("cp.async.wait_group 0;\n");
        }
        __syncthreads();

        __half* As = sm + (it & 1) * 9216;
        __half* Ws = As + 4608;
#pragma unroll
        for (int ks = 0; ks < 4; ks++) {
            wmma::fragment<wmma::matrix_a, 16, 16, 16, __half, wmma::row_major> a_frag[2];
            wmma::fragment<wmma::matrix_b, 16, 16, 16, __half, wmma::col_major> b_frag[2];
#pragma unroll
            for (int i = 0; i < 2; i++)
                wmma::load_matrix_sync(a_frag[i], &As[(wr * 32 + i * 16) * LDSH + ks * 16], LDSH);
#pragma unroll
            for (int j = 0; j < 2; j++)
                wmma::load_matrix_sync(b_frag[j], &Ws[(wc * 32 + j * 16) * LDSH + ks * 16], LDSH);
#pragma unroll
            for (int i = 0; i < 2; i++)
#pragma unroll
                for (int j = 0; j < 2; j++)
                    wmma::mma_sync(c_frag[i][j], a_frag[i], b_frag[j], c_frag[i][j]);
        }
        __syncthreads();
    }

    float* Cs = (float*)sm;
    const int LDCS = 68;
#pragma unroll
    for (int i = 0; i < 2; i++)
#pragma unroll
        for (int j = 0; j < 2; j++)
            wmma::store_matrix_sync(&Cs[(wr * 32 + i * 16) * LDCS + wc * 32 + j * 16],
                                    c_frag[i][j], LDCS, wmma::mem_row_major);
    __syncthreads();
#pragma unroll
    for (int i = 0; i < 32; i++) {
        int idx = tid + i * 128;
        int r = idx >> 6;
        int c = idx & 63;
        int m = m0 + r, n = n0 + c;
        float v = Cs[r * LDCS + c];
        if (bias) v += bias[n];
        C[(size_t)m * ldc + n] = v;
    }
}

// ---------------------------------------------------------------------------
// fp32 SGEMM 64x64 (prologue only: embed split-K, state0)
// ---------------------------------------------------------------------------
__global__ __launch_bounds__(256)
void sgemm64(const float* __restrict__ A, int lda,
             const float* __restrict__ W, int ldw,
             const float* __restrict__ bias,
             const float* __restrict__ addend, int ldadd,
             float* __restrict__ C, int ldc,
             int M, int N, int K, int Kc)
{
    __shared__ float As[16][68];
    __shared__ float Ws[16][68];

    int tid = threadIdx.x;
    int tx = tid & 15, ty = tid >> 4;
    int m0 = blockIdx.y * 64, n0 = blockIdx.x * 64;

    int kstart = 0, kend = K;
    float* Cp = C;
    if (Kc > 0) {
        kstart = blockIdx.z * Kc;
        kend = min(K, kstart + Kc);
        Cp = C + (size_t)blockIdx.z * (size_t)M * (size_t)ldc;
    }

    float acc[4][4];
#pragma unroll
    for (int i = 0; i < 4; i++)
#pragma unroll
        for (int j = 0; j < 4; j++) acc[i][j] = 0.f;

    for (int k0 = kstart; k0 < kend; k0 += 16) {
#pragma unroll
        for (int i = 0; i < 4; i++) {
            int idx = tid + i * 256;
            int r = idx >> 4, kk = idx & 15;
            int gk = k0 + kk;
            int gm = m0 + r;
            As[kk][r] = (gm < M && gk < kend) ? A[(size_t)gm * lda + gk] : 0.f;
            int gn = n0 + r;
            Ws[kk][r] = (gn < N && gk < kend) ? W[(size_t)gn * ldw + gk] : 0.f;
        }
        __syncthreads();
#pragma unroll
        for (int kk = 0; kk < 16; kk++) {
            float4 a = *(const float4*)&As[kk][ty * 4];
            float4 b = *(const float4*)&Ws[kk][tx * 4];
            float av[4] = {a.x, a.y, a.z, a.w};
            float bv[4] = {b.x, b.y, b.z, b.w};
#pragma unroll
            for (int i = 0; i < 4; i++)
#pragma unroll
                for (int j = 0; j < 4; j++)
                    acc[i][j] = fmaf(av[i], bv[j], acc[i][j]);
        }
        __syncthreads();
    }

#pragma unroll
    for (int i = 0; i < 4; i++) {
        int m = m0 + ty * 4 + i;
        if (m >= M) continue;
#pragma unroll
        for (int j = 0; j < 4; j++) {
            int n = n0 + tx * 4 + j;
            if (n >= N) continue;
            float v = acc[i][j];
            if (bias)   v += bias[n];
            if (addend) v += addend[(size_t)m * ldadd + n];
            Cp[(size_t)m * ldc + n] = v;
        }
    }
}

// ---------------------------------------------------------------------------
// Conversion / helper kernels
// ---------------------------------------------------------------------------
__global__ void cvt_h(const float* __restrict__ src, __half* __restrict__ dst, int n)
{
    int i = blockIdx.x * blockDim.x + threadIdx.x;
    if (i < n) dst[i] = __float2half_rn(src[i]);
}

__global__ void cvt_wih(const float* __restrict__ w)   // [1536][1024]
{
    int idx = blockIdx.x * blockDim.x + threadIdx.x;   // 1536*512
    if (idx >= 1536 * 512) return;
    int n = idx >> 9, k = idx & 511;
    g_hWih1[idx] = __float2half_rn(w[n * 1024 + k]);
    g_hWih2[idx] = __float2half_rn(w[n * 1024 + 512 + k]);
}

__global__ void wcat_fill(const float* __restrict__ sEmbed_w,
                          const float* __restrict__ sEmbed_b,
                          const float* __restrict__ w_hh,
                          const float* __restrict__ b_hh)
{
    int idx = blockIdx.x * blockDim.x + threadIdx.x;
    if (idx < 2048 * 512) {
        int n = idx >> 9;
        float v = (n < 512) ? sEmbed_w[idx] : w_hh[idx - 512 * 512];
        g_hWcat[idx] = __float2half_rn(v);
    }
    if (idx < 2048)
        g_bcat[idx] = (idx < 512) ? sEmbed_b[idx] : b_hh[idx - 512];
}

__global__ void splitk_reduce(const float* __restrict__ bias)
{
    int idx = blockIdx.x * blockDim.x + threadIdx.x;   // 256*300
    if (idx >= 256 * 300) return;
    float s = 0.f;
#pragma unroll
    for (int z = 0; z < 16; z++) s += g_EbufPart[z * (256 * 300) + idx];
    g_emb[idx] = s + bias[idx % 300];
}

__global__ void yp_gather(const int* __restrict__ targets,
                          const float* __restrict__ tgt_emb)
{
    int idx = blockIdx.x * blockDim.x + threadIdx.x;   // 25*256*512
    if (idx >= TDEC * 256 * 512) return;
    int d = idx & 511;
    int row = idx >> 9;          // t*256 + b
    int b = row & 255;
    int t = row >> 8;
    int y = (t == 0) ? YDIM_ : targets[b * TDEC + (t - 1)];
    g_hYp[idx] = __float2half_rn(tgt_emb[(size_t)y * 512 + d]);
}

// ---------------------------------------------------------------------------
// Fused attention + GI + GRU:
//   alpha = softmax_t( w . tanh(sProj + xProj[t]) + wb )
//   gi    = GIY[t_step] + sum_t alpha_t * XW2[b*25+t]   (context GEMM folded)
//   gates (r,z,n) with gh from g_C1, state update -> fp32 + fp16 states.
// One block per batch element, 256 threads.
// ---------------------------------------------------------------------------
__global__ __launch_bounds__(256)
void attn_gru(const float* __restrict__ GIYt,
              const float* __restrict__ state_in,
              float* __restrict__ state_out,
              __half* __restrict__ hstate_out,
              const float* __restrict__ wEmbed_w,
              const float* __restrict__ wEmbed_b)
{
    int b = blockIdx.x;
    int tid = threadIdx.x;
    int lane = tid & 31, warp = tid >> 5;
    __shared__ float sP[512];
    __shared__ float sW[512];
    __shared__ float alpha[32];

    sP[tid]       = g_C1[b * 2048 + tid];
    sP[tid + 256] = g_C1[b * 2048 + 256 + tid];
    sW[tid]       = wEmbed_w[tid];
    sW[tid + 256] = wEmbed_w[tid + 256];
    float wb = wEmbed_b[0];
    __syncthreads();

    // energies: warp w handles t = w, w+8, w+16, w+24
    for (int t = warp; t < TENC; t += 8) {
        const float* xp = g_XP + (size_t)(b * TENC + t) * 512;
        float v = 0.f;
#pragma unroll
        for (int i = 0; i < 16; i++) {
            int d = lane + i * 32;
            v += sW[d] * tanhf(sP[d] + xp[d]);
        }
#pragma unroll
        for (int o = 16; o > 0; o >>= 1) v += __shfl_xor_sync(0xffffffffu, v, o);
        if (lane == 0) alpha[t] = v + wb;
    }
    __syncthreads();

    if (tid < 32) {
        float ev = (tid < TENC) ? alpha[tid] : -1e30f;
        float m = ev;
#pragma unroll
        for (int o = 16; o > 0; o >>= 1) m = fmaxf(m, __shfl_xor_sync(0xffffffffu, m, o));
        float ex = (tid < TENC) ? __expf(ev - m) : 0.f;
        float s = ex;
#pragma unroll
        for (int o = 16; o > 0; o >>= 1) s += __shfl_xor_sync(0xffffffffu, s, o);
        if (tid < TENC) alpha[tid] = ex / s;
    }
    __syncthreads();

    // gates: thread handles hidden dims j = tid, tid+256
    const __half* xw = g_hXW2 + (size_t)b * TENC * 1536;
#pragma unroll
    for (int jj = 0; jj < 2; jj++) {
        int j = tid + jj * 256;
        float gr = GIYt[(size_t)b * 1536 + j];
        float gz = GIYt[(size_t)b * 1536 + 512 + j];
        float gn = GIYt[(size_t)b * 1536 + 1024 + j];
#pragma unroll
        for (int t = 0; t < TENC; t++) {
            float a = alpha[t];
            const __half* row = xw + (size_t)t * 1536;
            gr = fmaf(a, __half2float(row[j]),        gr);
            gz = fmaf(a, __half2float(row[512 + j]),  gz);
            gn = fmaf(a, __half2float(row[1024 + j]), gn);
        }
        float hr = g_C1[b * 2048 + 512 + j];
        float hz = g_C1[b * 2048 + 1024 + j];
        float hn = g_C1[b * 2048 + 1536 + j];
        float r = 1.f / (1.f + __expf(-(gr + hr)));
        float z = 1.f / (1.f + __expf(-(gz + hz)));
        float n = tanhf(gn + r * hn);
        float v = (1.f - z) * n + z * state_in[(size_t)b * 512 + j];
        state_out[(size_t)b * 512 + j]  = v;
        hstate_out[(size_t)b * 512 + j] = __float2half_rn(v);
    }
}

// ---------------------------------------------------------------------------
// Launch
// ---------------------------------------------------------------------------
extern "C" void kernel_launch(void* const* d_in, const int* in_sizes, int n_in,
                              void* d_out, int out_size)
{
    int off = (n_in > 19) ? 1 : 0;
    const float* x          = (const float*)d_in[0];
    const int*   targets    = (const int*)  d_in[1];
    const float* eEmbed_w   = (const float*)d_in[2 + off];
    const float* eEmbed_b   = (const float*)d_in[3 + off];
    const float* embed_fc_w = (const float*)d_in[4 + off];
    const float* embed_fc_b = (const float*)d_in[5 + off];
    const float* sEmbed_w   = (const float*)d_in[6 + off];
    const float* sEmbed_b   = (const float*)d_in[7 + off];
    const float* xEmbed_w   = (const float*)d_in[8 + off];
    const float* xEmbed_b   = (const float*)d_in[9 + off];
    const float* wEmbed_w   = (const float*)d_in[10 + off];
    const float* wEmbed_b   = (const float*)d_in[11 + off];
    const float* tgt_emb    = (const float*)d_in[12 + off];
    const float* gru_w_ih   = (const float*)d_in[13 + off];
    const float* gru_w_hh   = (const float*)d_in[14 + off];
    const float* gru_b_ih   = (const float*)d_in[15 + off];
    const float* gru_b_hh   = (const float*)d_in[16 + off];
    const float* fc_w       = (const float*)d_in[17 + off];
    const float* fc_b       = (const float*)d_in[18 + off];
    float* out = (float*)d_out;

    float *pbcat, *pEbufPart, *pemb, *pXP, *pGIY, *pXW2f, *pstates, *pC1;
    __half *phX, *phXw, *phYp, *phfcw, *phWcat, *phWih1, *phWih2, *phXW2, *phstates;
    cudaGetSymbolAddress((void**)&pbcat,     g_bcat);
    cudaGetSymbolAddress((void**)&pEbufPart, g_EbufPart);
    cudaGetSymbolAddress((void**)&pemb,      g_emb);
    cudaGetSymbolAddress((void**)&pXP,       g_XP);
    cudaGetSymbolAddress((void**)&pGIY,      g_GIY);
    cudaGetSymbolAddress((void**)&pXW2f,     g_XW2f);
    cudaGetSymbolAddress((void**)&pstates,   g_states);
    cudaGetSymbolAddress((void**)&pC1,       g_C1);
    cudaGetSymbolAddress((void**)&phX,       g_hX);
    cudaGetSymbolAddress((void**)&phXw,      g_hXw);
    cudaGetSymbolAddress((void**)&phYp,      g_hYp);
    cudaGetSymbolAddress((void**)&phfcw,     g_hfcw);
    cudaGetSymbolAddress((void**)&phWcat,    g_hWcat);
    cudaGetSymbolAddress((void**)&phWih1,    g_hWih1);
    cudaGetSymbolAddress((void**)&phWih2,    g_hWih2);
    cudaGetSymbolAddress((void**)&phXW2,     g_hXW2);
    cudaGetSymbolAddress((void**)&phstates,  g_hstates);

    // ---- Prologue: conversions + loop-invariant work ----
    wcat_fill<<<4096, 256>>>(sEmbed_w, sEmbed_b, gru_w_hh, gru_b_hh);
    cvt_h<<<(6400 * 512 + 255) / 256, 256>>>(x, phX, 6400 * 512);
    cvt_h<<<(YDIM_ * 512 + 255) / 256, 256>>>(fc_w, phfcw, YDIM_ * 512);
    cvt_h<<<(512 * 512 + 255) / 256, 256>>>(xEmbed_w, phXw, 512 * 512);
    cvt_wih<<<(1536 * 512 + 255) / 256, 256>>>(gru_w_ih);

    // embed = x_flat @ eEmbed_w.T  (K=12800, split-K 16-way, fp32)
    sgemm64<<<dim3(5, 4, 16), 256>>>(x, TENC * XDIM_, eEmbed_w, TENC * XDIM_,
                                     nullptr, nullptr, 0,
                                     pEbufPart, 300, 256, 300, TENC * XDIM_, 800);
    splitk_reduce<<<300, 256>>>(eEmbed_b);

    // state0 = emb @ embed_fc_w.T  (K=300, fp32) -> also fp16 copy
    sgemm64<<<dim3(8, 4), 256>>>(pemb, 300, embed_fc_w, 300, embed_fc_b,
                                 nullptr, 0, pstates, 512, 256, 512, 300, 0);
    cvt_h<<<(256 * 512 + 255) / 256, 256>>>(pstates, phstates, 256 * 512);

    // xProj = x @ xEmbed_w.T  (fp16 wmma)
    hgemm128<<<dim3(4, 50), 128>>>(phX, 512, phXw, 512, xEmbed_b,
                                   pXP, 512, 6400, 512, 512, 0);

    // yProj gather, GIY = Yp @ Wih1^T + b_ih
    yp_gather<<<12800, 256>>>(targets, tgt_emb);
    hgemm128<<<dim3(12, 50), 128>>>(phYp, 512, phWih1, 512, gru_b_ih,
                                    pGIY, 1536, 6400, 1536, 512, 0);

    // XW2 = x @ Wih2^T (loop-invariant context-GEMM factor), then fp16 copy
    hgemm128<<<dim3(12, 50), 128>>>(phX, 512, phWih2, 512, nullptr,
                                    pXW2f, 1536, 6400, 1536, 512, 0);
    cvt_h<<<(6400 * 1536 + 255) / 256, 256>>>(pXW2f, phXW2, 6400 * 1536);

    // ---- Sequential decode loop: 2 kernels per step ----
    for (int t = 0; t < TDEC; t++) {
        const __half* hstate_in = phstates + (size_t)t * (256 * 512);
        const float*  state_in  = pstates  + (size_t)t * (256 * 512);
        float*  state_out  = pstates  + (size_t)(t + 1) * (256 * 512);
        __half* hstate_out = phstates + (size_t)(t + 1) * (256 * 512);

        // [sProj | gh] = state @ [sEmbed_w ; w_hh].T   (256 x 2048 x 512)
        hgemm_small<<<dim3(32, 4), 128>>>(hstate_in, 512, phWcat, 512, pbcat,
                                          pC1, 2048, 512);

        // fused attention + gi (alpha . XW2) + GRU gates -> states[t+1]
        attn_gru<<<256, 256>>>(pGIY + (size_t)t * (256 * 1536),
                               state_in, state_out, hstate_out,
                               wEmbed_w, wEmbed_b);
    }

    // ---- Epilogue: batched fc over all 25 states (fp16 wmma, permuted) ----
    hgemm128<<<dim3(52, 50), 128>>>(phstates + 256 * 512, 512, phfcw, 512, fc_b,
                                    out, 0, 6400, YDIM_, 512, 1);
}

// round 17
// speedup vs baseline: 5.5425x; 1.0828x over previous
#include <cstdint>
#include <cuda_runtime.h>
#include <cuda_fp16.h>
#include <mma.h>

using namespace nvcuda;

// Problem constants
#define BB      256
#define TENC    25
#define XDIM_   512
#define SDIM_   512
#define ADIM_   512
#define YDIM_   6625
#define TDEC    25
#define EMBIN   300

// ---------------------------------------------------------------------------
// Static device scratch
// ---------------------------------------------------------------------------
__device__ __align__(256) float  g_bcat[2048];
__device__ __align__(256) float  g_EbufPart[16 * 256 * 300];
__device__ __align__(256) float  g_emb[256 * 300];
__device__ __align__(256) float  g_XP[6400 * 512];        // xProj (fp32)
__device__ __align__(256) float  g_GIY[6400 * 1536];      // gi (yProj part + b_ih)
__device__ __align__(256) float  g_states[26 * 256 * 512];// fp32 master states
__device__ __align__(256) float  g_C1[256 * 2048];        // [sProj | gh]
// fp16 GEMM operands
__device__ __align__(256) __half g_hX[6400 * 512];
__device__ __align__(256) __half g_hXw[512 * 512];
__device__ __align__(256) __half g_hYp[6400 * 512];
__device__ __align__(256) __half g_hfcw[6625 * 512];
__device__ __align__(256) __half g_hWcat[2048 * 512];     // [sEmbed_w ; w_hh]
__device__ __align__(256) __half g_hWih1[1536 * 512];     // w_ih[:, 0:512]
__device__ __align__(256) __half g_hWih2[1536 * 512];     // w_ih[:, 512:1024]
__device__ __align__(256) __half g_hXW2[6400 * 1536];     // x @ w_ih2^T (fp16, direct)
__device__ __align__(256) __half g_hstates[26 * 256 * 512];

// ---------------------------------------------------------------------------
// cp.async helper
// ---------------------------------------------------------------------------
__device__ __forceinline__ void cp_async16(void* smem_dst, const void* gptr, bool pred)
{
    unsigned int sa = (unsigned int)__cvta_generic_to_shared(smem_dst);
    int bytes = pred ? 16 : 0;
    asm volatile("cp.async.ca.shared.global [%0], [%1], 16, %2;\n"
                 :: "r"(sa), "l"(gptr), "r"(bytes));
}

// ---------------------------------------------------------------------------
// fp16 wmma GEMM (NT): out = A @ W^T + bias. Block 128x128, 4 warps (2x2),
// warp tile 64x64, BK=32, 2-stage cp.async.
// Output modes: C!=null fp32 (direct frag stores if interior non-permuted,
// else staged; permuted = fc scatter). Ch!=null: fp16 output via staged
// convert (used for XW2 -> no fp32 round-trip).
// ---------------------------------------------------------------------------
__global__ __launch_bounds__(128)
void hgemm128(const __half* __restrict__ A, int lda,
              const __half* __restrict__ W, int ldw,
              const float* __restrict__ bias,
              float* __restrict__ C, __half* __restrict__ Ch, int ldc,
              int M, int N, int K, int permuted)
{
    __shared__ __align__(16) __half sm[20480];   // 40 KB; stage s at s*10240
    const int LDSH = 40;

    int tid  = threadIdx.x;
    int warp = tid >> 5;
    int wr   = warp >> 1;
    int wc   = warp & 1;
    int m0 = blockIdx.y * 128;
    int n0 = blockIdx.x * 128;

    {
        float* Bs = (float*)sm;      // [16][136]
        const int LDB = 136;
        for (int i = tid; i < 16 * 128; i += 128) {
            int r = i >> 7, c = i & 127;
            int n = n0 + c;
            Bs[r * LDB + c] = (bias && n < N) ? bias[n] : 0.f;
        }
        __syncthreads();
    }
    wmma::fragment<wmma::accumulator, 16, 16, 16, float> c_frag[4][4];
    {
        float* Bs = (float*)sm;
        const int LDB = 136;
#pragma unroll
        for (int j = 0; j < 4; j++) {
            wmma::load_matrix_sync(c_frag[0][j], &Bs[wc * 64 + j * 16], LDB, wmma::mem_row_major);
#pragma unroll
            for (int i = 1; i < 4; i++)
#pragma unroll
                for (int t = 0; t < c_frag[0][j].num_elements; t++)
                    c_frag[i][j].x[t] = c_frag[0][j].x[t];
        }
        __syncthreads();
    }

    int nIter = K >> 5;

    auto load_stage = [&](int k0, int s) {
        __half* As = sm + s * 10240;
        __half* Ws = As + 5120;
#pragma unroll
        for (int i = 0; i < 4; i++) {
            int idx = tid + i * 128;
            int r   = idx >> 2;
            int c16 = idx & 3;
            cp_async16(&As[r * LDSH + c16 * 8], &A[(size_t)(m0 + r) * lda + k0 + c16 * 8], true);
            int gn = n0 + r;
            cp_async16(&Ws[r * LDSH + c16 * 8], &W[(size_t)gn * ldw + k0 + c16 * 8], gn < N);
        }
        asm volatile("cp.async.commit_group;\n");
    };

    load_stage(0, 0);

    for (int it = 0; it < nIter; it++) {
        if (it + 1 < nIter) {
            load_stage((it + 1) << 5, (it + 1) & 1);
            asm volatile("cp.async.wait_group 1;\n");
        } else {
            asm volatile("cp.async.wait_group 0;\n");
        }
        __syncthreads();

        __half* As = sm + (it & 1) * 10240;
        __half* Ws = As + 5120;
#pragma unroll
        for (int ks = 0; ks < 2; ks++) {
            wmma::fragment<wmma::matrix_a, 16, 16, 16, __half, wmma::row_major> a_frag[4];
            wmma::fragment<wmma::matrix_b, 16, 16, 16, __half, wmma::col_major> b_frag[4];
#pragma unroll
            for (int i = 0; i < 4; i++)
                wmma::load_matrix_sync(a_frag[i], &As[(wr * 64 + i * 16) * LDSH + ks * 16], LDSH);
#pragma unroll
            for (int j = 0; j < 4; j++)
                wmma::load_matrix_sync(b_frag[j], &Ws[(wc * 64 + j * 16) * LDSH + ks * 16], LDSH);
#pragma unroll
            for (int i = 0; i < 4; i++)
#pragma unroll
                for (int j = 0; j < 4; j++)
                    wmma::mma_sync(c_frag[i][j], a_frag[i], b_frag[j], c_frag[i][j]);
        }
        __syncthreads();
    }

    if (Ch == nullptr && !permuted && n0 + 128 <= N) {
        // fp32 direct fragment stores
#pragma unroll
        for (int i = 0; i < 4; i++) {
            int m = m0 + wr * 64 + i * 16;
#pragma unroll
            for (int j = 0; j < 4; j++) {
                int n = n0 + wc * 64 + j * 16;
                wmma::store_matrix_sync(&C[(size_t)m * ldc + n],
                                        c_frag[i][j], ldc, wmma::mem_row_major);
            }
        }
    } else {
        // staged path (fp32 permuted/edge, or fp16 output)
        float* Cs = (float*)sm;
        const int LDCS = 132;
#pragma unroll
        for (int p = 0; p < 2; p++) {
            if (wr == p) {
#pragma unroll
                for (int i = 0; i < 4; i++)
#pragma unroll
                    for (int j = 0; j < 4; j++)
                        wmma::store_matrix_sync(&Cs[(i * 16) * LDCS + wc * 64 + j * 16],
                                                c_frag[i][j], LDCS, wmma::mem_row_major);
            }
            __syncthreads();
            if (Ch) {
                // fp16 output, __half2 stores (ldc even, n0 even)
#pragma unroll
                for (int i = 0; i < 32; i++) {
                    int idx = tid + i * 128;    // 0..4095 (pairs)
                    int r = idx >> 6;
                    int c2 = idx & 63;
                    int m = m0 + p * 64 + r;
                    int n = n0 + c2 * 2;
                    if (n < N) {
                        __half2 h = __floats2half2_rn(Cs[r * LDCS + c2 * 2],
                                                      Cs[r * LDCS + c2 * 2 + 1]);
                        *(__half2*)&Ch[(size_t)m * ldc + n] = h;
                    }
                }
            } else {
#pragma unroll
                for (int i = 0; i < 64; i++) {
                    int idx = tid + i * 128;
                    int r = idx >> 7;
                    int c = idx & 127;
                    int m = m0 + p * 64 + r;
                    int n = n0 + c;
                    if (n < N) {
                        float v = Cs[r * LDCS + c];
                        if (permuted) {
                            int b = m & 255;
                            int t = m >> 8;
                            C[(size_t)b * (TDEC * YDIM_) + (size_t)t * YDIM_ + n] = v;
                        } else {
                            C[(size_t)m * ldc + n] = v;
                        }
                    }
                }
            }
            __syncthreads();
        }
    }
}

// ---------------------------------------------------------------------------
// fp16 wmma GEMM (NT) small: block 64x64, 4 warps, warp tile 32x32, BK=64,
// 2-stage cp.async. C = A @ W^T (+bias[n]). K % 64 == 0.
// ---------------------------------------------------------------------------
__global__ __launch_bounds__(128)
void hgemm_small(const __half* __restrict__ A, int lda,
                 const __half* __restrict__ W, int ldw,
                 const float* __restrict__ bias,
                 float* __restrict__ C, int ldc, int K)
{
    __shared__ __align__(16) __half sm[18432];
    const int LDSH = 72;

    int tid  = threadIdx.x;
    int warp = tid >> 5;
    int wr   = warp >> 1;
    int wc   = warp & 1;
    int m0 = blockIdx.y * 64;
    int n0 = blockIdx.x * 64;

    wmma::fragment<wmma::accumulator, 16, 16, 16, float> c_frag[2][2];
#pragma unroll
    for (int i = 0; i < 2; i++)
#pragma unroll
        for (int j = 0; j < 2; j++)
            wmma::fill_fragment(c_frag[i][j], 0.0f);

    int nIter = K >> 6;

    auto load_stage = [&](int k0, int s) {
        __half* As = sm + s * 9216;
        __half* Ws = As + 4608;
#pragma unroll
        for (int i = 0; i < 4; i++) {
            int idx = tid + i * 128;
            int r   = idx >> 3;
            int c16 = idx & 7;
            cp_async16(&As[r * LDSH + c16 * 8], &A[(size_t)(m0 + r) * lda + k0 + c16 * 8], true);
            cp_async16(&Ws[r * LDSH + c16 * 8], &W[(size_t)(n0 + r) * ldw + k0 + c16 * 8], true);
        }
        asm volatile("cp.async.commit_group;\n");
    };

    load_stage(0, 0);

    for (int it = 0; it < nIter; it++) {
        if (it + 1 < nIter) {
            load_stage((it + 1) << 6, (it + 1) & 1);
            asm volatile("cp.async.wait_group 1;\n");
        } else {
            asm volatile("cp.async.wait_group 0;\n");
        }
        __syncthreads();

        __half* As = sm + (it & 1) * 9216;
        __half* Ws = As + 4608;
#pragma unroll
        for (int ks = 0; ks < 4; ks++) {
            wmma::fragment<wmma::matrix_a, 16, 16, 16, __half, wmma::row_major> a_frag[2];
            wmma::fragment<wmma::matrix_b, 16, 16, 16, __half, wmma::col_major> b_frag[2];
#pragma unroll
            for (int i = 0; i < 2; i++)
                wmma::load_matrix_sync(a_frag[i], &As[(wr * 32 + i * 16) * LDSH + ks * 16], LDSH);
#pragma unroll
            for (int j = 0; j < 2; j++)
                wmma::load_matrix_sync(b_frag[j], &Ws[(wc * 32 + j * 16) * LDSH + ks * 16], LDSH);
#pragma unroll
            for (int i = 0; i < 2; i++)
#pragma unroll
                for (int j = 0; j < 2; j++)
                    wmma::mma_sync(c_frag[i][j], a_frag[i], b_frag[j], c_frag[i][j]);
        }
        __syncthreads();
    }

    float* Cs = (float*)sm;
    const int LDCS = 68;
#pragma unroll
    for (int i = 0; i < 2; i++)
#pragma unroll
        for (int j = 0; j < 2; j++)
            wmma::store_matrix_sync(&Cs[(wr * 32 + i * 16) * LDCS + wc * 32 + j * 16],
                                    c_frag[i][j], LDCS, wmma::mem_row_major);
    __syncthreads();
#pragma unroll
    for (int i = 0; i < 32; i++) {
        int idx = tid + i * 128;
        int r = idx >> 6;
        int c = idx & 63;
        int m = m0 + r, n = n0 + c;
        float v = Cs[r * LDCS + c];
        if (bias) v += bias[n];
        C[(size_t)m * ldc + n] = v;
    }
}

// ---------------------------------------------------------------------------
// fp32 SGEMM 64x64 (prologue only: embed split-K, state0)
// ---------------------------------------------------------------------------
__global__ __launch_bounds__(256)
void sgemm64(const float* __restrict__ A, int lda,
             const float* __restrict__ W, int ldw,
             const float* __restrict__ bias,
             const float* __restrict__ addend, int ldadd,
             float* __restrict__ C, int ldc,
             int M, int N, int K, int Kc)
{
    __shared__ float As[16][68];
    __shared__ float Ws[16][68];

    int tid = threadIdx.x;
    int tx = tid & 15, ty = tid >> 4;
    int m0 = blockIdx.y * 64, n0 = blockIdx.x * 64;

    int kstart = 0, kend = K;
    float* Cp = C;
    if (Kc > 0) {
        kstart = blockIdx.z * Kc;
        kend = min(K, kstart + Kc);
        Cp = C + (size_t)blockIdx.z * (size_t)M * (size_t)ldc;
    }

    float acc[4][4];
#pragma unroll
    for (int i = 0; i < 4; i++)
#pragma unroll
        for (int j = 0; j < 4; j++) acc[i][j] = 0.f;

    for (int k0 = kstart; k0 < kend; k0 += 16) {
#pragma unroll
        for (int i = 0; i < 4; i++) {
            int idx = tid + i * 256;
            int r = idx >> 4, kk = idx & 15;
            int gk = k0 + kk;
            int gm = m0 + r;
            As[kk][r] = (gm < M && gk < kend) ? A[(size_t)gm * lda + gk] : 0.f;
            int gn = n0 + r;
            Ws[kk][r] = (gn < N && gk < kend) ? W[(size_t)gn * ldw + gk] : 0.f;
        }
        __syncthreads();
#pragma unroll
        for (int kk = 0; kk < 16; kk++) {
            float4 a = *(const float4*)&As[kk][ty * 4];
            float4 b = *(const float4*)&Ws[kk][tx * 4];
            float av[4] = {a.x, a.y, a.z, a.w};
            float bv[4] = {b.x, b.y, b.z, b.w};
#pragma unroll
            for (int i = 0; i < 4; i++)
#pragma unroll
                for (int j = 0; j < 4; j++)
                    acc[i][j] = fmaf(av[i], bv[j], acc[i][j]);
        }
        __syncthreads();
    }

#pragma unroll
    for (int i = 0; i < 4; i++) {
        int m = m0 + ty * 4 + i;
        if (m >= M) continue;
#pragma unroll
        for (int j = 0; j < 4; j++) {
            int n = n0 + tx * 4 + j;
            if (n >= N) continue;
            float v = acc[i][j];
            if (bias)   v += bias[n];
            if (addend) v += addend[(size_t)m * ldadd + n];
            Cp[(size_t)m * ldc + n] = v;
        }
    }
}

// ---------------------------------------------------------------------------
// Conversion / helper kernels
// ---------------------------------------------------------------------------
__global__ void cvt_h(const float* __restrict__ src, __half* __restrict__ dst, int n)
{
    int i = blockIdx.x * blockDim.x + threadIdx.x;
    if (i < n) dst[i] = __float2half_rn(src[i]);
}

__global__ void cvt_wih(const float* __restrict__ w)   // [1536][1024]
{
    int idx = blockIdx.x * blockDim.x + threadIdx.x;   // 1536*512
    if (idx >= 1536 * 512) return;
    int n = idx >> 9, k = idx & 511;
    g_hWih1[idx] = __float2half_rn(w[n * 1024 + k]);
    g_hWih2[idx] = __float2half_rn(w[n * 1024 + 512 + k]);
}

__global__ void wcat_fill(const float* __restrict__ sEmbed_w,
                          const float* __restrict__ sEmbed_b,
                          const float* __restrict__ w_hh,
                          const float* __restrict__ b_hh)
{
    int idx = blockIdx.x * blockDim.x + threadIdx.x;
    if (idx < 2048 * 512) {
        int n = idx >> 9;
        float v = (n < 512) ? sEmbed_w[idx] : w_hh[idx - 512 * 512];
        g_hWcat[idx] = __float2half_rn(v);
    }
    if (idx < 2048)
        g_bcat[idx] = (idx < 512) ? sEmbed_b[idx] : b_hh[idx - 512];
}

__global__ void splitk_reduce(const float* __restrict__ bias)
{
    int idx = blockIdx.x * blockDim.x + threadIdx.x;   // 256*300
    if (idx >= 256 * 300) return;
    float s = 0.f;
#pragma unroll
    for (int z = 0; z < 16; z++) s += g_EbufPart[z * (256 * 300) + idx];
    g_emb[idx] = s + bias[idx % 300];
}

__global__ void yp_gather(const int* __restrict__ targets,
                          const float* __restrict__ tgt_emb)
{
    int idx = blockIdx.x * blockDim.x + threadIdx.x;   // 25*256*512
    if (idx >= TDEC * 256 * 512) return;
    int d = idx & 511;
    int row = idx >> 9;          // t*256 + b
    int b = row & 255;
    int t = row >> 8;
    int y = (t == 0) ? YDIM_ : targets[b * TDEC + (t - 1)];
    g_hYp[idx] = __float2half_rn(tgt_emb[(size_t)y * 512 + d]);
}

// ---------------------------------------------------------------------------
// Fused attention + GI + GRU (vectorized):
//   alpha = softmax_t( w . tanh(sProj + xProj[t]) + wb )
//   gi    = GIY[t_step] + sum_t alpha_t * XW2[b*25+t]   (context GEMM folded)
//   gates with gh from g_C1, state update -> fp32 + fp16 states.
// One block per batch element, 256 threads; each thread owns dims (2*tid,2*tid+1).
// ---------------------------------------------------------------------------
__global__ __launch_bounds__(256)
void attn_gru(const float* __restrict__ GIYt,
              const float* __restrict__ state_in,
              float* __restrict__ state_out,
              __half* __restrict__ hstate_out,
              const float* __restrict__ wEmbed_w,
              const float* __restrict__ wEmbed_b)
{
    int b = blockIdx.x;
    int tid = threadIdx.x;
    int lane = tid & 31, warp = tid >> 5;
    __shared__ float sP[512];
    __shared__ float sW[512];
    __shared__ float alpha[32];

    sP[tid]       = g_C1[b * 2048 + tid];
    sP[tid + 256] = g_C1[b * 2048 + 256 + tid];
    sW[tid]       = wEmbed_w[tid];
    sW[tid + 256] = wEmbed_w[tid + 256];
    float wb = wEmbed_b[0];
    __syncthreads();

    // energies: warp w handles t = w, w+8, w+16, w+24
    for (int t = warp; t < TENC; t += 8) {
        const float* xp = g_XP + (size_t)(b * TENC + t) * 512;
        float v = 0.f;
#pragma unroll
        for (int i = 0; i < 16; i++) {
            int d = lane + i * 32;
            v += sW[d] * tanhf(sP[d] + xp[d]);
        }
#pragma unroll
        for (int o = 16; o > 0; o >>= 1) v += __shfl_xor_sync(0xffffffffu, v, o);
        if (lane == 0) alpha[t] = v + wb;
    }
    __syncthreads();

    if (tid < 32) {
        float ev = (tid < TENC) ? alpha[tid] : -1e30f;
        float m = ev;
#pragma unroll
        for (int o = 16; o > 0; o >>= 1) m = fmaxf(m, __shfl_xor_sync(0xffffffffu, m, o));
        float ex = (tid < TENC) ? __expf(ev - m) : 0.f;
        float s = ex;
#pragma unroll
        for (int o = 16; o > 0; o >>= 1) s += __shfl_xor_sync(0xffffffffu, s, o);
        if (tid < TENC) alpha[tid] = ex / s;
    }
    __syncthreads();

    // gates: thread owns hidden dims j0 = 2*tid, j0+1 (half2/float2 path)
    int j0 = tid * 2;
    const __half* xw = g_hXW2 + (size_t)b * TENC * 1536;
    float2 gr = *(const float2*)&GIYt[(size_t)b * 1536 + j0];
    float2 gz = *(const float2*)&GIYt[(size_t)b * 1536 + 512 + j0];
    float2 gn = *(const float2*)&GIYt[(size_t)b * 1536 + 1024 + j0];
#pragma unroll
    for (int t = 0; t < TENC; t++) {
        float a = alpha[t];
        const __half* row = xw + (size_t)t * 1536;
        float2 fr = __half22float2(*(const __half2*)&row[j0]);
        float2 fz = __half22float2(*(const __half2*)&row[512 + j0]);
        float2 fn = __half22float2(*(const __half2*)&row[1024 + j0]);
        gr.x = fmaf(a, fr.x, gr.x); gr.y = fmaf(a, fr.y, gr.y);
        gz.x = fmaf(a, fz.x, gz.x); gz.y = fmaf(a, fz.y, gz.y);
        gn.x = fmaf(a, fn.x, gn.x); gn.y = fmaf(a, fn.y, gn.y);
    }
    float2 hr = *(const float2*)&g_C1[b * 2048 + 512 + j0];
    float2 hz = *(const float2*)&g_C1[b * 2048 + 1024 + j0];
    float2 hn = *(const float2*)&g_C1[b * 2048 + 1536 + j0];
    float2 si = *(const float2*)&state_in[(size_t)b * 512 + j0];
    float r0 = 1.f / (1.f + __expf(-(gr.x + hr.x)));
    float r1 = 1.f / (1.f + __expf(-(gr.y + hr.y)));
    float z0 = 1.f / (1.f + __expf(-(gz.x + hz.x)));
    float z1 = 1.f / (1.f + __expf(-(gz.y + hz.y)));
    float n0 = tanhf(gn.x + r0 * hn.x);
    float n1 = tanhf(gn.y + r1 * hn.y);
    float v0 = (1.f - z0) * n0 + z0 * si.x;
    float v1 = (1.f - z1) * n1 + z1 * si.y;
    *(float2*)&state_out[(size_t)b * 512 + j0] = make_float2(v0, v1);
    *(__half2*)&hstate_out[(size_t)b * 512 + j0] = __floats2half2_rn(v0, v1);
}

// ---------------------------------------------------------------------------
// Launch
// ---------------------------------------------------------------------------
extern "C" void kernel_launch(void* const* d_in, const int* in_sizes, int n_in,
                              void* d_out, int out_size)
{
    int off = (n_in > 19) ? 1 : 0;
    const float* x          = (const float*)d_in[0];
    const int*   targets    = (const int*)  d_in[1];
    const float* eEmbed_w   = (const float*)d_in[2 + off];
    const float* eEmbed_b   = (const float*)d_in[3 + off];
    const float* embed_fc_w = (const float*)d_in[4 + off];
    const float* embed_fc_b = (const float*)d_in[5 + off];
    const float* sEmbed_w   = (const float*)d_in[6 + off];
    const float* sEmbed_b   = (const float*)d_in[7 + off];
    const float* xEmbed_w   = (const float*)d_in[8 + off];
    const float* xEmbed_b   = (const float*)d_in[9 + off];
    const float* wEmbed_w   = (const float*)d_in[10 + off];
    const float* wEmbed_b   = (const float*)d_in[11 + off];
    const float* tgt_emb    = (const float*)d_in[12 + off];
    const float* gru_w_ih   = (const float*)d_in[13 + off];
    const float* gru_w_hh   = (const float*)d_in[14 + off];
    const float* gru_b_ih   = (const float*)d_in[15 + off];
    const float* gru_b_hh   = (const float*)d_in[16 + off];
    const float* fc_w       = (const float*)d_in[17 + off];
    const float* fc_b       = (const float*)d_in[18 + off];
    float* out = (float*)d_out;

    float *pbcat, *pEbufPart, *pemb, *pXP, *pGIY, *pstates, *pC1;
    __half *phX, *phXw, *phYp, *phfcw, *phWcat, *phWih1, *phWih2, *phXW2, *phstates;
    cudaGetSymbolAddress((void**)&pbcat,     g_bcat);
    cudaGetSymbolAddress((void**)&pEbufPart, g_EbufPart);
    cudaGetSymbolAddress((void**)&pemb,      g_emb);
    cudaGetSymbolAddress((void**)&pXP,       g_XP);
    cudaGetSymbolAddress((void**)&pGIY,      g_GIY);
    cudaGetSymbolAddress((void**)&pstates,   g_states);
    cudaGetSymbolAddress((void**)&pC1,       g_C1);
    cudaGetSymbolAddress((void**)&phX,       g_hX);
    cudaGetSymbolAddress((void**)&phXw,      g_hXw);
    cudaGetSymbolAddress((void**)&phYp,      g_hYp);
    cudaGetSymbolAddress((void**)&phfcw,     g_hfcw);
    cudaGetSymbolAddress((void**)&phWcat,    g_hWcat);
    cudaGetSymbolAddress((void**)&phWih1,    g_hWih1);
    cudaGetSymbolAddress((void**)&phWih2,    g_hWih2);
    cudaGetSymbolAddress((void**)&phXW2,     g_hXW2);
    cudaGetSymbolAddress((void**)&phstates,  g_hstates);

    // ---- Prologue: conversions + loop-invariant work ----
    wcat_fill<<<4096, 256>>>(sEmbed_w, sEmbed_b, gru_w_hh, gru_b_hh);
    cvt_h<<<(6400 * 512 + 255) / 256, 256>>>(x, phX, 6400 * 512);
    cvt_h<<<(YDIM_ * 512 + 255) / 256, 256>>>(fc_w, phfcw, YDIM_ * 512);
    cvt_h<<<(512 * 512 + 255) / 256, 256>>>(xEmbed_w, phXw, 512 * 512);
    cvt_wih<<<(1536 * 512 + 255) / 256, 256>>>(gru_w_ih);

    // embed = x_flat @ eEmbed_w.T  (K=12800, split-K 16-way, fp32)
    sgemm64<<<dim3(5, 4, 16), 256>>>(x, TENC * XDIM_, eEmbed_w, TENC * XDIM_,
                                     nullptr, nullptr, 0,
                                     pEbufPart, 300, 256, 300, TENC * XDIM_, 800);
    splitk_reduce<<<300, 256>>>(eEmbed_b);

    // state0 = emb @ embed_fc_w.T  (K=300, fp32) -> also fp16 copy
    sgemm64<<<dim3(8, 4), 256>>>(pemb, 300, embed_fc_w, 300, embed_fc_b,
                                 nullptr, 0, pstates, 512, 256, 512, 300, 0);
    cvt_h<<<(256 * 512 + 255) / 256, 256>>>(pstates, phstates, 256 * 512);

    // xProj = x @ xEmbed_w.T  (fp16 wmma, fp32 out)
    hgemm128<<<dim3(4, 50), 128>>>(phX, 512, phXw, 512, xEmbed_b,
                                   pXP, nullptr, 512, 6400, 512, 512, 0);

    // yProj gather, GIY = Yp @ Wih1^T + b_ih (fp32 out)
    yp_gather<<<12800, 256>>>(targets, tgt_emb);
    hgemm128<<<dim3(12, 50), 128>>>(phYp, 512, phWih1, 512, gru_b_ih,
                                    pGIY, nullptr, 1536, 6400, 1536, 512, 0);

    // XW2 = x @ Wih2^T, fp16 output DIRECT (no fp32 round-trip)
    hgemm128<<<dim3(12, 50), 128>>>(phX, 512, phWih2, 512, nullptr,
                                    nullptr, phXW2, 1536, 6400, 1536, 512, 0);

    // ---- Sequential decode loop: 2 kernels per step ----
    for (int t = 0; t < TDEC; t++) {
        const __half* hstate_in = phstates + (size_t)t * (256 * 512);
        const float*  state_in  = pstates  + (size_t)t * (256 * 512);
        float*  state_out  = pstates  + (size_t)(t + 1) * (256 * 512);
        __half* hstate_out = phstates + (size_t)(t + 1) * (256 * 512);

        // [sProj | gh] = state @ [sEmbed_w ; w_hh].T   (256 x 2048 x 512)
        hgemm_small<<<dim3(32, 4), 128>>>(hstate_in, 512, phWcat, 512, pbcat,
                                          pC1, 2048, 512);

        // fused attention + gi (alpha . XW2) + GRU gates -> states[t+1]
        attn_gru<<<256, 256>>>(pGIY + (size_t)t * (256 * 1536),
                               state_in, state_out, hstate_out,
                               wEmbed_w, wEmbed_b);
    }

    // ---- Epilogue: batched fc over all 25 states (fp16 wmma, permuted) ----
    hgemm128<<<dim3(52, 50), 128>>>(phstates + 256 * 512, 512, phfcw, 512, fc_b,
                                    out, nullptr, 0, 6400, YDIM_, 512, 1);
}